// round 12
// baseline (speedup 1.0000x reference)
#include <cuda_runtime.h>
#include <cstdint>
#include <cstddef>

// ---------------- problem constants -----------------------------------------
#define NTOK   65536          // B*S
#define DMODEL 512
#define HID    2048

// ---------------- scratch (static device globals; no allocation) ------------
__device__ float g_norm [(size_t)NTOK * DMODEL];
__device__ float g_xattn[(size_t)NTOK * DMODEL];
__device__ float g_h    [(size_t)NTOK * HID];
__device__ float g_y    [(size_t)NTOK * DMODEL];
// pre-rounded (tf32) weights: attn_w | next_w | fc1_w | fc2_w
#define WR_ATTN 0
#define WR_NEXT (512 * 512)
#define WR_FC1  (2 * 512 * 512)
#define WR_FC2  (WR_FC1 + 8 * 2048 * 512)
__device__ float g_wr[(size_t)(2 * 512 * 512 + 2 * 8 * 2048 * 512)];

// ---------------- PTX helpers ------------------------------------------------
__device__ __forceinline__ uint32_t smem_u32(const void* p) {
    uint32_t a;
    asm("{ .reg .u64 t; cvta.to.shared.u64 t, %1; cvt.u32.u64 %0, t; }"
        : "=r"(a) : "l"(p));
    return a;
}
__device__ __forceinline__ float to_tf32(float x) {
    float r;
    asm("cvt.rna.tf32.f32 %0, %1;" : "=f"(r) : "f"(x));
    return r;
}
__device__ __forceinline__ void cp16(uint32_t dst, const void* src) {
    asm volatile("cp.async.cg.shared.global [%0], [%1], 16;"
                 :: "r"(dst), "l"(src) : "memory");
}
__device__ __forceinline__ void cp_commit() {
    asm volatile("cp.async.commit_group;" ::: "memory");
}
template<int N>
__device__ __forceinline__ void cp_wait() {
    asm volatile("cp.async.wait_group %0;" :: "n"(N) : "memory");
}
__device__ __forceinline__ void ldsm4(uint32_t& r0, uint32_t& r1,
                                      uint32_t& r2, uint32_t& r3, uint32_t addr) {
    asm volatile("ldmatrix.sync.aligned.m8n8.x4.shared.b16 {%0,%1,%2,%3}, [%4];"
                 : "=r"(r0), "=r"(r1), "=r"(r2), "=r"(r3) : "r"(addr));
}
__device__ __forceinline__ void mma_tf32(float* d, const uint32_t* a,
                                         uint32_t b0, uint32_t b1) {
    asm volatile(
        "mma.sync.aligned.m16n8k8.row.col.f32.tf32.tf32.f32 "
        "{%0,%1,%2,%3}, {%4,%5,%6,%7}, {%8,%9}, {%0,%1,%2,%3};"
        : "+f"(d[0]), "+f"(d[1]), "+f"(d[2]), "+f"(d[3])
        : "r"(a[0]), "r"(a[1]), "r"(a[2]), "r"(a[3]), "r"(b0), "r"(b1));
}
__device__ __forceinline__ float gelu_erf(float x) {
    return 0.5f * x * (1.0f + erff(x * 0.70710678118654752f));
}
__device__ __forceinline__ uint32_t swz(uint32_t off) {
    return off ^ ((off >> 3) & 0x70);
}

// ---------------- fused weight pre-round (fp32 -> tf32 bits), 1 launch -------
#define N4_SMALL (512 * 512 / 4)           // 65536 float4
#define N4_BIG   (8 * 2048 * 512 / 4)      // 2097152 float4
__global__ void __launch_bounds__(256) round_all(
    const float4* __restrict__ s0, const float4* __restrict__ s1,
    const float4* __restrict__ s2, const float4* __restrict__ s3,
    float4* __restrict__ dst)
{
    size_t i = (size_t)blockIdx.x * 256 + threadIdx.x;
    const float4* src;
    size_t off;
    if (i < N4_SMALL)                       { src = s0; off = i; }
    else if (i < 2 * N4_SMALL)              { src = s1; off = i - N4_SMALL; }
    else if (i < 2 * N4_SMALL + N4_BIG)     { src = s2; off = i - 2 * N4_SMALL; }
    else if (i < 2 * N4_SMALL + 2 * N4_BIG) { src = s3; off = i - 2 * N4_SMALL - N4_BIG; }
    else return;
    float4 v = src[off];
    v.x = to_tf32(v.x); v.y = to_tf32(v.y);
    v.z = to_tf32(v.z); v.w = to_tf32(v.w);
    dst[i] = v;
}

// ---------------- LayerNorm (warp per token, tf32-rounded output) ------------
__global__ void __launch_bounds__(256) ln_kernel(
    const float* __restrict__ x, const float* __restrict__ g,
    const float* __restrict__ b, float* __restrict__ out)
{
    const int warp = threadIdx.x >> 5;
    const int lane = threadIdx.x & 31;
    const int token = blockIdx.x * 8 + warp;
    const float* row = x + (size_t)token * DMODEL;

    float4 v[4];
    float s = 0.f, ss = 0.f;
#pragma unroll
    for (int q = 0; q < 4; q++) {
        v[q] = *(const float4*)(row + (size_t)(q * 32 + lane) * 4);
        s  += v[q].x + v[q].y + v[q].z + v[q].w;
        ss  = fmaf(v[q].x, v[q].x, ss);
        ss  = fmaf(v[q].y, v[q].y, ss);
        ss  = fmaf(v[q].z, v[q].z, ss);
        ss  = fmaf(v[q].w, v[q].w, ss);
    }
#pragma unroll
    for (int off = 16; off > 0; off >>= 1) {
        s  += __shfl_xor_sync(0xffffffffu, s,  off);
        ss += __shfl_xor_sync(0xffffffffu, ss, off);
    }
    const float mu  = s * (1.0f / DMODEL);
    const float var = ss * (1.0f / DMODEL) - mu * mu;
    const float rs  = rsqrtf(var + 1e-5f);

    float* orow = out + (size_t)token * DMODEL;
#pragma unroll
    for (int q = 0; q < 4; q++) {
        const int c = (q * 32 + lane) * 4;
        float4 gg = *(const float4*)(g + c);
        float4 bb = *(const float4*)(b + c);
        float4 o;
        o.x = to_tf32((v[q].x - mu) * rs * gg.x + bb.x);
        o.y = to_tf32((v[q].y - mu) * rs * gg.y + bb.y);
        o.z = to_tf32((v[q].z - mu) * rs * gg.z + bb.z);
        o.w = to_tf32((v[q].w - mu) * rs * gg.w + bb.w);
        *(float4*)(orow + c) = o;
    }
}

// ---------------- tf32 mma.sync GEMM (templated tile config) -----------------
// C[r,c] = sum_k A[r,k] * W[e][c,k] + bias[e][c] (+resid[r,c]) (gelu)
// A and W must be pre-rounded to tf32 bit patterns.
// Warp tile is always 64x64 (4:1 MMA:ldsm). Requires (BMT/64)*(BNT/64)==TPB/32.
template<int BMT, int BNT, int BKT, int TPB, bool GELU, bool RESID, bool ROUND_OUT>
__global__ void __launch_bounds__(TPB, 1)
tc_gemm(const float* __restrict__ A, const float* __restrict__ W,
        const float* __restrict__ bias, const float* __restrict__ resid,
        float* __restrict__ C, int K, int OUTD,
        size_t w_estride, int b_estride)
{
    constexpr int MQ      = BMT / 64;          // warp quarters in M
    constexpr int NBLK    = BKT / 32;          // 128B column blocks per stage
    constexpr int A_BLKb  = BMT * 128;
    constexpr int B_BLKb  = BNT * 128;
    constexpr int A_BYTESb = NBLK * A_BLKb;
    constexpr int STGb    = NBLK * (A_BLKb + B_BLKb);
    constexpr int AC      = BMT * 8 / TPB;     // A cp16 per thread per blk
    constexpr int BC      = BNT * 8 / TPB;     // B cp16 per thread per blk
    constexpr int RS      = TPB / 8;           // staging row stride

    extern __shared__ char smem[];
    const uint32_t sb = smem_u32(smem);
    const int tid  = threadIdx.x;
    const int wid  = tid >> 5;
    const int lane = tid & 31;
    const int row0 = blockIdx.y * BMT;
    const int col0 = blockIdx.x * BNT;

    const int e = (row0 >> 12) & 7;            // expert id (4096-token chunks)
    const float* Wp = W + (w_estride ? (size_t)e * w_estride : 0);
    const float* Bp = bias + (b_estride ? e * b_estride : 0);

    const int wm = wid % MQ;                   // M quarter -> 64 rows
    const int wn = wid / MQ;                   // N quarter -> 64 cols

    // ldmatrix lane-derived components
    const int aRow  = (lane & 7) + ((lane >> 3) & 1) * 8;
    const int aBSel = (lane >> 4) * 16;
    const int bRow  = (lane & 7) + ((lane >> 4) & 1) * 8;
    const int bBSel = ((lane >> 3) & 1) * 16;

    // hoisted swizzle: swz(R*128 + t) = R*128 + (t ^ ((R&7)<<4)), t<128
    const uint32_t xA = (uint32_t)((aRow & 7) << 4);
    const uint32_t xB = (uint32_t)((bRow & 7) << 4);
    uint32_t rowA[4], rowB[4], ktA[4], ktB[4];
#pragma unroll
    for (int i = 0; i < 4; i++)
        rowA[i] = (uint32_t)((wm * 64 + i * 16 + aRow) * 128);
#pragma unroll
    for (int j = 0; j < 4; j++)
        rowB[j] = (uint32_t)((wn * 64 + j * 16 + bRow) * 128);
#pragma unroll
    for (int t = 0; t < 4; t++) {
        ktA[t] = (uint32_t)(t * 32 + aBSel) ^ xA;
        ktB[t] = (uint32_t)(t * 32 + bBSel) ^ xB;
    }

    // cp.async staging indices
    const int sr = tid >> 3;                   // 0..RS-1 base row
    const int sq = tid & 7;                    // 16B chunk in 128B row
    const uint32_t stgOff = swz((uint32_t)(sr * 128 + sq * 16));

    const float* aGm = A  + (size_t)(row0 + sr) * K + sq * 4;
    const float* bGm = Wp + (size_t)(col0 + sr) * K + sq * 4;

    float acc[4][8][4];
#pragma unroll
    for (int i = 0; i < 4; i++)
#pragma unroll
        for (int j = 0; j < 8; j++)
#pragma unroll
            for (int q = 0; q < 4; q++) acc[i][j][q] = 0.f;

    const int nst = K / BKT;

    auto issue = [&](int s) {
        const uint32_t base = sb + (uint32_t)(s & 1) * STGb;
        const int kOff = s * BKT;
#pragma unroll
        for (int blk = 0; blk < NBLK; blk++) {
#pragma unroll
            for (int i = 0; i < AC; i++)
                cp16(base + blk * A_BLKb + stgOff + (uint32_t)(i * RS * 128),
                     aGm + (size_t)i * RS * K + kOff + blk * 32);
#pragma unroll
            for (int i = 0; i < BC; i++)
                cp16(base + A_BYTESb + blk * B_BLKb + stgOff + (uint32_t)(i * RS * 128),
                     bGm + (size_t)i * RS * K + kOff + blk * 32);
        }
        cp_commit();
    };

    issue(0);

    for (int s = 0; s < nst; ++s) {
        cp_wait<0>();
        __syncthreads();                        // buffer s&1 ready, s-1 consumed
        if (s + 1 < nst) issue(s + 1);          // fill the freed buffer

        const uint32_t stgA = sb + (uint32_t)(s & 1) * STGb;
#pragma unroll
        for (int kk = 0; kk < NBLK * 4; ++kk) {
            const int blk = kk >> 2;
            const int t   = kk & 3;
            const uint32_t sbA = stgA + (uint32_t)(blk * A_BLKb) + ktA[t];
            const uint32_t sbB = stgA + A_BYTESb + (uint32_t)(blk * B_BLKb) + ktB[t];
            uint32_t af[4][4], bf[4][4];
#pragma unroll
            for (int i = 0; i < 4; ++i)
                ldsm4(af[i][0], af[i][1], af[i][2], af[i][3], sbA + rowA[i]);
#pragma unroll
            for (int j = 0; j < 4; ++j)
                ldsm4(bf[j][0], bf[j][1], bf[j][2], bf[j][3], sbB + rowB[j]);
#pragma unroll
            for (int i = 0; i < 4; ++i)
#pragma unroll
                for (int j = 0; j < 4; ++j) {
                    mma_tf32(acc[i][2 * j],     af[i], bf[j][0], bf[j][1]);
                    mma_tf32(acc[i][2 * j + 1], af[i], bf[j][2], bf[j][3]);
                }
        }
    }

    // ---- epilogue: direct float2 stores --------------------------------------
    const int gr  = lane >> 2;
    const int ctg = lane & 3;
#pragma unroll
    for (int j = 0; j < 8; ++j) {
        const int col = col0 + wn * 64 + j * 8 + 2 * ctg;
        float2 bv = *(const float2*)(Bp + col);
#pragma unroll
        for (int i = 0; i < 4; ++i) {
            const int ra = row0 + wm * 64 + i * 16 + gr;
            const int rb = ra + 8;
            float2 o0, o1;
            o0.x = acc[i][j][0] + bv.x;  o0.y = acc[i][j][1] + bv.y;
            o1.x = acc[i][j][2] + bv.x;  o1.y = acc[i][j][3] + bv.y;
            if (RESID) {
                float2 r0 = *(const float2*)(resid + (size_t)ra * OUTD + col);
                float2 r1 = *(const float2*)(resid + (size_t)rb * OUTD + col);
                o0.x += r0.x; o0.y += r0.y;
                o1.x += r1.x; o1.y += r1.y;
            }
            if (GELU) {
                o0.x = gelu_erf(o0.x); o0.y = gelu_erf(o0.y);
                o1.x = gelu_erf(o1.x); o1.y = gelu_erf(o1.y);
            }
            if (ROUND_OUT) {
                o0.x = to_tf32(o0.x); o0.y = to_tf32(o0.y);
                o1.x = to_tf32(o1.x); o1.y = to_tf32(o1.y);
            }
            *(float2*)(C + (size_t)ra * OUTD + col) = o0;
            *(float2*)(C + (size_t)rb * OUTD + col) = o1;
        }
    }
}

// ---------------- config aliases ----------------------------------------------
// big config: 256x256x32, 512 threads, smem 128 KB (fc1, fc2)
#define SMEM_BIG  (2 * (256 * 128 + 256 * 128))            // 131072
// small config: 128x256x64, 256 threads, smem 192 KB (attn, next)
#define SMEM_SML  (2 * (2 * 128 * 128 + 2 * 256 * 128))    // 196608

// ---------------- launch ------------------------------------------------------
extern "C" void kernel_launch(void* const* d_in, const int* in_sizes, int n_in,
                              void* d_out, int out_size)
{
    const float* x      = (const float*)d_in[0];
    const float* ln_g   = (const float*)d_in[1];
    const float* ln_b   = (const float*)d_in[2];
    const float* attn_w = (const float*)d_in[3];
    const float* attn_b = (const float*)d_in[4];
    /* gate_w d_in[5] unused — gating does not affect the output path */
    const float* fc1_w  = (const float*)d_in[6];
    const float* fc1_b  = (const float*)d_in[7];
    const float* fc2_w  = (const float*)d_in[8];
    const float* fc2_b  = (const float*)d_in[9];
    const float* next_w = (const float*)d_in[10];
    const float* next_b = (const float*)d_in[11];
    float* out = (float*)d_out;

    void *p_norm, *p_xattn, *p_h, *p_y, *p_wr;
    cudaGetSymbolAddress(&p_norm,  g_norm);
    cudaGetSymbolAddress(&p_xattn, g_xattn);
    cudaGetSymbolAddress(&p_h,     g_h);
    cudaGetSymbolAddress(&p_y,     g_y);
    cudaGetSymbolAddress(&p_wr,    g_wr);
    float* norm  = (float*)p_norm;
    float* xattn = (float*)p_xattn;
    float* hbuf  = (float*)p_h;
    float* ybuf  = (float*)p_y;
    float* wr    = (float*)p_wr;

    auto kAttn = tc_gemm<128, 256, 64, 256, false, true,  true>;
    auto kFc1  = tc_gemm<256, 256, 32, 512, true,  false, true>;
    auto kFc2  = tc_gemm<256, 256, 32, 512, false, false, true>;
    auto kNext = tc_gemm<128, 256, 64, 256, true,  false, false>;

    cudaFuncSetAttribute(kAttn, cudaFuncAttributeMaxDynamicSharedMemorySize, SMEM_SML);
    cudaFuncSetAttribute(kFc1,  cudaFuncAttributeMaxDynamicSharedMemorySize, SMEM_BIG);
    cudaFuncSetAttribute(kFc2,  cudaFuncAttributeMaxDynamicSharedMemorySize, SMEM_BIG);
    cudaFuncSetAttribute(kNext, cudaFuncAttributeMaxDynamicSharedMemorySize, SMEM_SML);

    // 0) pre-round all weights to tf32 (single fused launch)
    {
        const size_t total4 = 2 * (size_t)N4_SMALL + 2 * (size_t)N4_BIG;
        round_all<<<(unsigned)((total4 + 255) / 256), 256>>>(
            (const float4*)attn_w, (const float4*)next_w,
            (const float4*)fc1_w,  (const float4*)fc2_w, (float4*)wr);
    }

    // 1) LayerNorm (tf32-rounded output)
    ln_kernel<<<NTOK / 8, 256>>>(x, ln_g, ln_b, norm);

    // 2) attn linear + residual (output rounded: feeds fc1)
    kAttn<<<dim3(DMODEL / 256, NTOK / 128), 256, SMEM_SML>>>(
        norm, wr + WR_ATTN, attn_b, x, xattn, DMODEL, DMODEL, 0, 0);

    // 3) fc1 + gelu (per-expert; output rounded: feeds fc2)
    kFc1<<<dim3(HID / 256, NTOK / 256), 512, SMEM_BIG>>>(
        xattn, wr + WR_FC1, fc1_b, nullptr, hbuf, DMODEL, HID,
        (size_t)HID * DMODEL, HID);

    // 4) fc2 (per-expert; output rounded: feeds next)
    kFc2<<<dim3(DMODEL / 256, NTOK / 256), 512, SMEM_BIG>>>(
        hbuf, wr + WR_FC2, fc2_b, nullptr, ybuf, HID, DMODEL,
        (size_t)DMODEL * HID, DMODEL);

    // 5) next linear + gelu (final output, no rounding)
    kNext<<<dim3(DMODEL / 256, NTOK / 128), 256, SMEM_SML>>>(
        ybuf, wr + WR_NEXT, next_b, nullptr, out, DMODEL, DMODEL, 0, 0);
}

// round 13
// speedup vs baseline: 3.0047x; 3.0047x over previous
#include <cuda_runtime.h>
#include <cstdint>
#include <cstddef>

// ---------------- problem constants -----------------------------------------
#define NTOK   65536          // B*S
#define DMODEL 512
#define HID    2048

// ---------------- scratch (static device globals; no allocation) ------------
__device__ float g_norm [(size_t)NTOK * DMODEL];
__device__ float g_xattn[(size_t)NTOK * DMODEL];
__device__ float g_h    [(size_t)NTOK * HID];
__device__ float g_y    [(size_t)NTOK * DMODEL];
// pre-rounded (tf32) weights: attn_w | next_w | fc1_w | fc2_w
#define WR_ATTN 0
#define WR_NEXT (512 * 512)
#define WR_FC1  (2 * 512 * 512)
#define WR_FC2  (WR_FC1 + 8 * 2048 * 512)
__device__ float g_wr[(size_t)(2 * 512 * 512 + 2 * 8 * 2048 * 512)];

// ---------------- PTX helpers ------------------------------------------------
__device__ __forceinline__ uint32_t smem_u32(const void* p) {
    uint32_t a;
    asm("{ .reg .u64 t; cvta.to.shared.u64 t, %1; cvt.u32.u64 %0, t; }"
        : "=r"(a) : "l"(p));
    return a;
}
__device__ __forceinline__ float to_tf32(float x) {
    float r;
    asm("cvt.rna.tf32.f32 %0, %1;" : "=f"(r) : "f"(x));
    return r;
}
__device__ __forceinline__ void cp16(uint32_t dst, const void* src) {
    asm volatile("cp.async.cg.shared.global [%0], [%1], 16;"
                 :: "r"(dst), "l"(src) : "memory");
}
__device__ __forceinline__ void cp_commit() {
    asm volatile("cp.async.commit_group;" ::: "memory");
}
template<int N>
__device__ __forceinline__ void cp_wait() {
    asm volatile("cp.async.wait_group %0;" :: "n"(N) : "memory");
}
__device__ __forceinline__ void ldsm4(uint32_t& r0, uint32_t& r1,
                                      uint32_t& r2, uint32_t& r3, uint32_t addr) {
    asm volatile("ldmatrix.sync.aligned.m8n8.x4.shared.b16 {%0,%1,%2,%3}, [%4];"
                 : "=r"(r0), "=r"(r1), "=r"(r2), "=r"(r3) : "r"(addr));
}
__device__ __forceinline__ void mma_tf32(float* d, const uint32_t* a,
                                         uint32_t b0, uint32_t b1) {
    asm volatile(
        "mma.sync.aligned.m16n8k8.row.col.f32.tf32.tf32.f32 "
        "{%0,%1,%2,%3}, {%4,%5,%6,%7}, {%8,%9}, {%0,%1,%2,%3};"
        : "+f"(d[0]), "+f"(d[1]), "+f"(d[2]), "+f"(d[3])
        : "r"(a[0]), "r"(a[1]), "r"(a[2]), "r"(a[3]), "r"(b0), "r"(b1));
}
__device__ __forceinline__ float gelu_erf(float x) {
    return 0.5f * x * (1.0f + erff(x * 0.70710678118654752f));
}
__device__ __forceinline__ uint32_t swz(uint32_t off) {
    return off ^ ((off >> 3) & 0x70);
}

// ---------------- fused weight pre-round (fp32 -> tf32 bits), 1 launch -------
#define N4_SMALL (512 * 512 / 4)           // 65536 float4
#define N4_BIG   (8 * 2048 * 512 / 4)      // 2097152 float4
__global__ void __launch_bounds__(256) round_all(
    const float4* __restrict__ s0, const float4* __restrict__ s1,
    const float4* __restrict__ s2, const float4* __restrict__ s3,
    float4* __restrict__ dst)
{
    size_t i = (size_t)blockIdx.x * 256 + threadIdx.x;
    const float4* src;
    size_t off;
    if (i < N4_SMALL)                       { src = s0; off = i; }
    else if (i < 2 * N4_SMALL)              { src = s1; off = i - N4_SMALL; }
    else if (i < 2 * N4_SMALL + N4_BIG)     { src = s2; off = i - 2 * N4_SMALL; }
    else if (i < 2 * N4_SMALL + 2 * N4_BIG) { src = s3; off = i - 2 * N4_SMALL - N4_BIG; }
    else return;
    float4 v = src[off];
    v.x = to_tf32(v.x); v.y = to_tf32(v.y);
    v.z = to_tf32(v.z); v.w = to_tf32(v.w);
    dst[i] = v;
}

// ---------------- LayerNorm (warp per token, tf32-rounded output) ------------
__global__ void __launch_bounds__(256) ln_kernel(
    const float* __restrict__ x, const float* __restrict__ g,
    const float* __restrict__ b, float* __restrict__ out)
{
    const int warp = threadIdx.x >> 5;
    const int lane = threadIdx.x & 31;
    const int token = blockIdx.x * 8 + warp;
    const float* row = x + (size_t)token * DMODEL;

    float4 v[4];
    float s = 0.f, ss = 0.f;
#pragma unroll
    for (int q = 0; q < 4; q++) {
        v[q] = *(const float4*)(row + (size_t)(q * 32 + lane) * 4);
        s  += v[q].x + v[q].y + v[q].z + v[q].w;
        ss  = fmaf(v[q].x, v[q].x, ss);
        ss  = fmaf(v[q].y, v[q].y, ss);
        ss  = fmaf(v[q].z, v[q].z, ss);
        ss  = fmaf(v[q].w, v[q].w, ss);
    }
#pragma unroll
    for (int off = 16; off > 0; off >>= 1) {
        s  += __shfl_xor_sync(0xffffffffu, s,  off);
        ss += __shfl_xor_sync(0xffffffffu, ss, off);
    }
    const float mu  = s * (1.0f / DMODEL);
    const float var = ss * (1.0f / DMODEL) - mu * mu;
    const float rs  = rsqrtf(var + 1e-5f);

    float* orow = out + (size_t)token * DMODEL;
#pragma unroll
    for (int q = 0; q < 4; q++) {
        const int c = (q * 32 + lane) * 4;
        float4 gg = *(const float4*)(g + c);
        float4 bb = *(const float4*)(b + c);
        float4 o;
        o.x = to_tf32((v[q].x - mu) * rs * gg.x + bb.x);
        o.y = to_tf32((v[q].y - mu) * rs * gg.y + bb.y);
        o.z = to_tf32((v[q].z - mu) * rs * gg.z + bb.z);
        o.w = to_tf32((v[q].w - mu) * rs * gg.w + bb.w);
        *(float4*)(orow + c) = o;
    }
}

// ---------------- tf32 mma.sync GEMM (templated tile config) -----------------
// C[r,c] = sum_k A[r,k] * W[e][c,k] + bias[e][c] (+resid[r,c]) (gelu)
// A and W must be pre-rounded to tf32 bit patterns.
// Warp tile is always 64x64 (4:1 MMA:ldsm). Requires (BMT/64)*(BNT/64)==TPB/32.
// MAXB = CTAs per SM for the occupancy hint.
template<int BMT, int BNT, int BKT, int TPB, int MAXB,
         bool GELU, bool RESID, bool ROUND_OUT>
__global__ void __launch_bounds__(TPB, MAXB)
tc_gemm(const float* __restrict__ A, const float* __restrict__ W,
        const float* __restrict__ bias, const float* __restrict__ resid,
        float* __restrict__ C, int K, int OUTD,
        size_t w_estride, int b_estride)
{
    constexpr int MQ      = BMT / 64;          // warp quarters in M
    constexpr int NBLK    = BKT / 32;          // 128B column blocks per stage
    constexpr int A_BLKb  = BMT * 128;
    constexpr int B_BLKb  = BNT * 128;
    constexpr int A_BYTESb = NBLK * A_BLKb;
    constexpr int STGb    = NBLK * (A_BLKb + B_BLKb);
    constexpr int AC      = BMT * 8 / TPB;     // A cp16 per thread per blk
    constexpr int BC      = BNT * 8 / TPB;     // B cp16 per thread per blk
    constexpr int RS      = TPB / 8;           // staging row stride

    extern __shared__ char smem[];
    const uint32_t sb = smem_u32(smem);
    const int tid  = threadIdx.x;
    const int wid  = tid >> 5;
    const int lane = tid & 31;
    const int row0 = blockIdx.y * BMT;
    const int col0 = blockIdx.x * BNT;

    const int e = (row0 >> 12) & 7;            // expert id (4096-token chunks)
    const float* Wp = W + (w_estride ? (size_t)e * w_estride : 0);
    const float* Bp = bias + (b_estride ? e * b_estride : 0);

    const int wm = wid % MQ;                   // M quarter -> 64 rows
    const int wn = wid / MQ;                   // N quarter -> 64 cols

    // ldmatrix lane-derived components
    const int aRow  = (lane & 7) + ((lane >> 3) & 1) * 8;
    const int aBSel = (lane >> 4) * 16;
    const int bRow  = (lane & 7) + ((lane >> 4) & 1) * 8;
    const int bBSel = ((lane >> 3) & 1) * 16;

    // hoisted swizzle: swz(R*128 + t) = R*128 + (t ^ ((R&7)<<4)), t<128
    const uint32_t xA = (uint32_t)((aRow & 7) << 4);
    const uint32_t xB = (uint32_t)((bRow & 7) << 4);
    uint32_t rowA[4], rowB[4], ktA[4], ktB[4];
#pragma unroll
    for (int i = 0; i < 4; i++)
        rowA[i] = (uint32_t)((wm * 64 + i * 16 + aRow) * 128);
#pragma unroll
    for (int j = 0; j < 4; j++)
        rowB[j] = (uint32_t)((wn * 64 + j * 16 + bRow) * 128);
#pragma unroll
    for (int t = 0; t < 4; t++) {
        ktA[t] = (uint32_t)(t * 32 + aBSel) ^ xA;
        ktB[t] = (uint32_t)(t * 32 + bBSel) ^ xB;
    }

    // cp.async staging indices
    const int sr = tid >> 3;                   // 0..RS-1 base row
    const int sq = tid & 7;                    // 16B chunk in 128B row
    const uint32_t stgOff = swz((uint32_t)(sr * 128 + sq * 16));

    const float* aGm = A  + (size_t)(row0 + sr) * K + sq * 4;
    const float* bGm = Wp + (size_t)(col0 + sr) * K + sq * 4;

    float acc[4][8][4];
#pragma unroll
    for (int i = 0; i < 4; i++)
#pragma unroll
        for (int j = 0; j < 8; j++)
#pragma unroll
            for (int q = 0; q < 4; q++) acc[i][j][q] = 0.f;

    const int nst = K / BKT;

    auto issue = [&](int s) {
        const uint32_t base = sb + (uint32_t)(s & 1) * STGb;
        const int kOff = s * BKT;
#pragma unroll
        for (int blk = 0; blk < NBLK; blk++) {
#pragma unroll
            for (int i = 0; i < AC; i++)
                cp16(base + blk * A_BLKb + stgOff + (uint32_t)(i * RS * 128),
                     aGm + (size_t)i * RS * K + kOff + blk * 32);
#pragma unroll
            for (int i = 0; i < BC; i++)
                cp16(base + A_BYTESb + blk * B_BLKb + stgOff + (uint32_t)(i * RS * 128),
                     bGm + (size_t)i * RS * K + kOff + blk * 32);
        }
        cp_commit();
    };

    issue(0);

    for (int s = 0; s < nst; ++s) {
        cp_wait<0>();
        __syncthreads();                        // buffer s&1 ready, s-1 consumed
        if (s + 1 < nst) issue(s + 1);          // fill the freed buffer

        const uint32_t stgA = sb + (uint32_t)(s & 1) * STGb;
#pragma unroll
        for (int kk = 0; kk < NBLK * 4; ++kk) {
            const int blk = kk >> 2;
            const int t   = kk & 3;
            const uint32_t sbA = stgA + (uint32_t)(blk * A_BLKb) + ktA[t];
            const uint32_t sbB = stgA + A_BYTESb + (uint32_t)(blk * B_BLKb) + ktB[t];
            uint32_t af[4][4], bf[4][4];
#pragma unroll
            for (int i = 0; i < 4; ++i)
                ldsm4(af[i][0], af[i][1], af[i][2], af[i][3], sbA + rowA[i]);
#pragma unroll
            for (int j = 0; j < 4; ++j)
                ldsm4(bf[j][0], bf[j][1], bf[j][2], bf[j][3], sbB + rowB[j]);
#pragma unroll
            for (int i = 0; i < 4; ++i)
#pragma unroll
                for (int j = 0; j < 4; ++j) {
                    mma_tf32(acc[i][2 * j],     af[i], bf[j][0], bf[j][1]);
                    mma_tf32(acc[i][2 * j + 1], af[i], bf[j][2], bf[j][3]);
                }
        }
    }

    // ---- epilogue: direct float2 stores --------------------------------------
    const int gr  = lane >> 2;
    const int ctg = lane & 3;
#pragma unroll
    for (int j = 0; j < 8; ++j) {
        const int col = col0 + wn * 64 + j * 8 + 2 * ctg;
        float2 bv = *(const float2*)(Bp + col);
#pragma unroll
        for (int i = 0; i < 4; ++i) {
            const int ra = row0 + wm * 64 + i * 16 + gr;
            const int rb = ra + 8;
            float2 o0, o1;
            o0.x = acc[i][j][0] + bv.x;  o0.y = acc[i][j][1] + bv.y;
            o1.x = acc[i][j][2] + bv.x;  o1.y = acc[i][j][3] + bv.y;
            if (RESID) {
                float2 r0 = *(const float2*)(resid + (size_t)ra * OUTD + col);
                float2 r1 = *(const float2*)(resid + (size_t)rb * OUTD + col);
                o0.x += r0.x; o0.y += r0.y;
                o1.x += r1.x; o1.y += r1.y;
            }
            if (GELU) {
                o0.x = gelu_erf(o0.x); o0.y = gelu_erf(o0.y);
                o1.x = gelu_erf(o1.x); o1.y = gelu_erf(o1.y);
            }
            if (ROUND_OUT) {
                o0.x = to_tf32(o0.x); o0.y = to_tf32(o0.y);
                o1.x = to_tf32(o1.x); o1.y = to_tf32(o1.y);
            }
            *(float2*)(C + (size_t)ra * OUTD + col) = o0;
            *(float2*)(C + (size_t)rb * OUTD + col) = o1;
        }
    }
}

// ---------------- config -------------------------------------------------------
// 128x128x32, 128 threads (4 warps, warp tile 64x64), 2 CTAs/SM
#define SMEM_CFG (2 * (128 * 128 + 128 * 128))    // 65536 bytes per CTA

// ---------------- launch ------------------------------------------------------
extern "C" void kernel_launch(void* const* d_in, const int* in_sizes, int n_in,
                              void* d_out, int out_size)
{
    const float* x      = (const float*)d_in[0];
    const float* ln_g   = (const float*)d_in[1];
    const float* ln_b   = (const float*)d_in[2];
    const float* attn_w = (const float*)d_in[3];
    const float* attn_b = (const float*)d_in[4];
    /* gate_w d_in[5] unused — gating does not affect the output path */
    const float* fc1_w  = (const float*)d_in[6];
    const float* fc1_b  = (const float*)d_in[7];
    const float* fc2_w  = (const float*)d_in[8];
    const float* fc2_b  = (const float*)d_in[9];
    const float* next_w = (const float*)d_in[10];
    const float* next_b = (const float*)d_in[11];
    float* out = (float*)d_out;

    void *p_norm, *p_xattn, *p_h, *p_y, *p_wr;
    cudaGetSymbolAddress(&p_norm,  g_norm);
    cudaGetSymbolAddress(&p_xattn, g_xattn);
    cudaGetSymbolAddress(&p_h,     g_h);
    cudaGetSymbolAddress(&p_y,     g_y);
    cudaGetSymbolAddress(&p_wr,    g_wr);
    float* norm  = (float*)p_norm;
    float* xattn = (float*)p_xattn;
    float* hbuf  = (float*)p_h;
    float* ybuf  = (float*)p_y;
    float* wr    = (float*)p_wr;

    auto kAttn = tc_gemm<128, 128, 32, 128, 2, false, true,  true>;
    auto kFc1  = tc_gemm<128, 128, 32, 128, 2, true,  false, true>;
    auto kFc2  = tc_gemm<128, 128, 32, 128, 2, false, false, true>;
    auto kNext = tc_gemm<128, 128, 32, 128, 2, true,  false, false>;

    cudaFuncSetAttribute(kAttn, cudaFuncAttributeMaxDynamicSharedMemorySize, SMEM_CFG);
    cudaFuncSetAttribute(kFc1,  cudaFuncAttributeMaxDynamicSharedMemorySize, SMEM_CFG);
    cudaFuncSetAttribute(kFc2,  cudaFuncAttributeMaxDynamicSharedMemorySize, SMEM_CFG);
    cudaFuncSetAttribute(kNext, cudaFuncAttributeMaxDynamicSharedMemorySize, SMEM_CFG);

    // 0) pre-round all weights to tf32 (single fused launch)
    {
        const size_t total4 = 2 * (size_t)N4_SMALL + 2 * (size_t)N4_BIG;
        round_all<<<(unsigned)((total4 + 255) / 256), 256>>>(
            (const float4*)attn_w, (const float4*)next_w,
            (const float4*)fc1_w,  (const float4*)fc2_w, (float4*)wr);
    }

    // 1) LayerNorm (tf32-rounded output)
    ln_kernel<<<NTOK / 8, 256>>>(x, ln_g, ln_b, norm);

    // 2) attn linear + residual (output rounded: feeds fc1)
    kAttn<<<dim3(DMODEL / 128, NTOK / 128), 128, SMEM_CFG>>>(
        norm, wr + WR_ATTN, attn_b, x, xattn, DMODEL, DMODEL, 0, 0);

    // 3) fc1 + gelu (per-expert; output rounded: feeds fc2)
    kFc1<<<dim3(HID / 128, NTOK / 128), 128, SMEM_CFG>>>(
        xattn, wr + WR_FC1, fc1_b, nullptr, hbuf, DMODEL, HID,
        (size_t)HID * DMODEL, HID);

    // 4) fc2 (per-expert; output rounded: feeds next)
    kFc2<<<dim3(DMODEL / 128, NTOK / 128), 128, SMEM_CFG>>>(
        hbuf, wr + WR_FC2, fc2_b, nullptr, ybuf, HID, DMODEL,
        (size_t)DMODEL * HID, DMODEL);

    // 5) next linear + gelu (final output, no rounding)
    kNext<<<dim3(DMODEL / 128, NTOK / 128), 128, SMEM_CFG>>>(
        ybuf, wr + WR_NEXT, next_b, nullptr, out, DMODEL, DMODEL, 0, 0);
}

// round 14
// speedup vs baseline: 3.0055x; 1.0002x over previous
#include <cuda_runtime.h>
#include <cstdint>
#include <cstddef>

// ---------------- problem constants -----------------------------------------
#define NTOK   65536          // B*S
#define DMODEL 512
#define HID    2048

// ---------------- scratch (static device globals; no allocation) ------------
__device__ float g_norm [(size_t)NTOK * DMODEL];
__device__ float g_xattn[(size_t)NTOK * DMODEL];
__device__ float g_h    [(size_t)NTOK * HID];
__device__ float g_y    [(size_t)NTOK * DMODEL];
// pre-rounded (tf32) weights: attn_w | next_w | fc1_w | fc2_w
#define WR_ATTN 0
#define WR_NEXT (512 * 512)
#define WR_FC1  (2 * 512 * 512)
#define WR_FC2  (WR_FC1 + 8 * 2048 * 512)
__device__ float g_wr[(size_t)(2 * 512 * 512 + 2 * 8 * 2048 * 512)];

// ---------------- PTX helpers ------------------------------------------------
__device__ __forceinline__ uint32_t smem_u32(const void* p) {
    uint32_t a;
    asm("{ .reg .u64 t; cvta.to.shared.u64 t, %1; cvt.u32.u64 %0, t; }"
        : "=r"(a) : "l"(p));
    return a;
}
__device__ __forceinline__ float to_tf32(float x) {
    float r;
    asm("cvt.rna.tf32.f32 %0, %1;" : "=f"(r) : "f"(x));
    return r;
}
__device__ __forceinline__ void cp16(uint32_t dst, const void* src) {
    asm volatile("cp.async.cg.shared.global [%0], [%1], 16;"
                 :: "r"(dst), "l"(src) : "memory");
}
__device__ __forceinline__ void cp_commit() {
    asm volatile("cp.async.commit_group;" ::: "memory");
}
template<int N>
__device__ __forceinline__ void cp_wait() {
    asm volatile("cp.async.wait_group %0;" :: "n"(N) : "memory");
}
__device__ __forceinline__ void ldsm4(uint32_t& r0, uint32_t& r1,
                                      uint32_t& r2, uint32_t& r3, uint32_t addr) {
    asm volatile("ldmatrix.sync.aligned.m8n8.x4.shared.b16 {%0,%1,%2,%3}, [%4];"
                 : "=r"(r0), "=r"(r1), "=r"(r2), "=r"(r3) : "r"(addr));
}
__device__ __forceinline__ void mma_tf32(float* d, const uint32_t* a,
                                         uint32_t b0, uint32_t b1) {
    asm volatile(
        "mma.sync.aligned.m16n8k8.row.col.f32.tf32.tf32.f32 "
        "{%0,%1,%2,%3}, {%4,%5,%6,%7}, {%8,%9}, {%0,%1,%2,%3};"
        : "+f"(d[0]), "+f"(d[1]), "+f"(d[2]), "+f"(d[3])
        : "r"(a[0]), "r"(a[1]), "r"(a[2]), "r"(a[3]), "r"(b0), "r"(b1));
}
__device__ __forceinline__ float gelu_erf(float x) {
    return 0.5f * x * (1.0f + erff(x * 0.70710678118654752f));
}
__device__ __forceinline__ uint32_t swz(uint32_t off) {
    return off ^ ((off >> 3) & 0x70);
}

// ---------------- fused weight pre-round (fp32 -> tf32 bits), 1 launch -------
#define N4_SMALL (512 * 512 / 4)           // 65536 float4
#define N4_BIG   (8 * 2048 * 512 / 4)      // 2097152 float4
__global__ void __launch_bounds__(256) round_all(
    const float4* __restrict__ s0, const float4* __restrict__ s1,
    const float4* __restrict__ s2, const float4* __restrict__ s3,
    float4* __restrict__ dst)
{
    size_t i = (size_t)blockIdx.x * 256 + threadIdx.x;
    const float4* src;
    size_t off;
    if (i < N4_SMALL)                       { src = s0; off = i; }
    else if (i < 2 * N4_SMALL)              { src = s1; off = i - N4_SMALL; }
    else if (i < 2 * N4_SMALL + N4_BIG)     { src = s2; off = i - 2 * N4_SMALL; }
    else if (i < 2 * N4_SMALL + 2 * N4_BIG) { src = s3; off = i - 2 * N4_SMALL - N4_BIG; }
    else return;
    float4 v = src[off];
    v.x = to_tf32(v.x); v.y = to_tf32(v.y);
    v.z = to_tf32(v.z); v.w = to_tf32(v.w);
    dst[i] = v;
}

// ---------------- LayerNorm (warp per token, tf32-rounded output) ------------
__global__ void __launch_bounds__(256) ln_kernel(
    const float* __restrict__ x, const float* __restrict__ g,
    const float* __restrict__ b, float* __restrict__ out)
{
    const int warp = threadIdx.x >> 5;
    const int lane = threadIdx.x & 31;
    const int token = blockIdx.x * 8 + warp;
    const float* row = x + (size_t)token * DMODEL;

    float4 v[4];
    float s = 0.f, ss = 0.f;
#pragma unroll
    for (int q = 0; q < 4; q++) {
        v[q] = *(const float4*)(row + (size_t)(q * 32 + lane) * 4);
        s  += v[q].x + v[q].y + v[q].z + v[q].w;
        ss  = fmaf(v[q].x, v[q].x, ss);
        ss  = fmaf(v[q].y, v[q].y, ss);
        ss  = fmaf(v[q].z, v[q].z, ss);
        ss  = fmaf(v[q].w, v[q].w, ss);
    }
#pragma unroll
    for (int off = 16; off > 0; off >>= 1) {
        s  += __shfl_xor_sync(0xffffffffu, s,  off);
        ss += __shfl_xor_sync(0xffffffffu, ss, off);
    }
    const float mu  = s * (1.0f / DMODEL);
    const float var = ss * (1.0f / DMODEL) - mu * mu;
    const float rs  = rsqrtf(var + 1e-5f);

    float* orow = out + (size_t)token * DMODEL;
#pragma unroll
    for (int q = 0; q < 4; q++) {
        const int c = (q * 32 + lane) * 4;
        float4 gg = *(const float4*)(g + c);
        float4 bb = *(const float4*)(b + c);
        float4 o;
        o.x = to_tf32((v[q].x - mu) * rs * gg.x + bb.x);
        o.y = to_tf32((v[q].y - mu) * rs * gg.y + bb.y);
        o.z = to_tf32((v[q].z - mu) * rs * gg.z + bb.z);
        o.w = to_tf32((v[q].w - mu) * rs * gg.w + bb.w);
        *(float4*)(orow + c) = o;
    }
}

// ---------------- tf32 mma.sync GEMM (templated tile config) -----------------
// C[r,c] = sum_k A[r,k] * W[e][c,k] + bias[e][c] (+resid[r,c]) (gelu)
// A and W must be pre-rounded to tf32 bit patterns.
// Warp tile is always 64x64 (4:1 MMA:ldsm). Requires (BMT/64)*(BNT/64)==TPB/32.
// 3-stage cp.async pipeline; MAXB = CTAs per SM occupancy hint.
template<int BMT, int BNT, int BKT, int TPB, int MAXB,
         bool GELU, bool RESID, bool ROUND_OUT>
__global__ void __launch_bounds__(TPB, MAXB)
tc_gemm(const float* __restrict__ A, const float* __restrict__ W,
        const float* __restrict__ bias, const float* __restrict__ resid,
        float* __restrict__ C, int K, int OUTD,
        size_t w_estride, int b_estride)
{
    constexpr int MQ      = BMT / 64;          // warp quarters in M
    constexpr int NBLK    = BKT / 32;          // 128B column blocks per stage
    constexpr int A_BLKb  = BMT * 128;
    constexpr int B_BLKb  = BNT * 128;
    constexpr int A_BYTESb = NBLK * A_BLKb;
    constexpr int STGb    = NBLK * (A_BLKb + B_BLKb);
    constexpr int AC      = BMT * 8 / TPB;     // A cp16 per thread per blk
    constexpr int BC      = BNT * 8 / TPB;     // B cp16 per thread per blk
    constexpr int RS      = TPB / 8;           // staging row stride
    constexpr int NSTG    = 3;                 // pipeline depth

    extern __shared__ char smem[];
    const uint32_t sb = smem_u32(smem);
    const int tid  = threadIdx.x;
    const int wid  = tid >> 5;
    const int lane = tid & 31;
    const int row0 = blockIdx.y * BMT;
    const int col0 = blockIdx.x * BNT;

    const int e = (row0 >> 12) & 7;            // expert id (4096-token chunks)
    const float* Wp = W + (w_estride ? (size_t)e * w_estride : 0);
    const float* Bp = bias + (b_estride ? e * b_estride : 0);

    const int wm = wid % MQ;                   // M quarter -> 64 rows
    const int wn = wid / MQ;                   // N quarter -> 64 cols

    // ldmatrix lane-derived components
    const int aRow  = (lane & 7) + ((lane >> 3) & 1) * 8;
    const int aBSel = (lane >> 4) * 16;
    const int bRow  = (lane & 7) + ((lane >> 4) & 1) * 8;
    const int bBSel = ((lane >> 3) & 1) * 16;

    // hoisted swizzle: swz(R*128 + t) = R*128 + (t ^ ((R&7)<<4)), t<128
    const uint32_t xA = (uint32_t)((aRow & 7) << 4);
    const uint32_t xB = (uint32_t)((bRow & 7) << 4);
    uint32_t rowA[4], rowB[4], ktA[4], ktB[4];
#pragma unroll
    for (int i = 0; i < 4; i++)
        rowA[i] = (uint32_t)((wm * 64 + i * 16 + aRow) * 128);
#pragma unroll
    for (int j = 0; j < 4; j++)
        rowB[j] = (uint32_t)((wn * 64 + j * 16 + bRow) * 128);
#pragma unroll
    for (int t = 0; t < 4; t++) {
        ktA[t] = (uint32_t)(t * 32 + aBSel) ^ xA;
        ktB[t] = (uint32_t)(t * 32 + bBSel) ^ xB;
    }

    // cp.async staging indices
    const int sr = tid >> 3;                   // 0..RS-1 base row
    const int sq = tid & 7;                    // 16B chunk in 128B row
    const uint32_t stgOff = swz((uint32_t)(sr * 128 + sq * 16));

    // running GMEM pointers (issues are strictly sequential in s)
    const float* aCur = A  + (size_t)(row0 + sr) * K + sq * 4;
    const float* bCur = Wp + (size_t)(col0 + sr) * K + sq * 4;

    float acc[4][8][4];
#pragma unroll
    for (int i = 0; i < 4; i++)
#pragma unroll
        for (int j = 0; j < 8; j++)
#pragma unroll
            for (int q = 0; q < 4; q++) acc[i][j][q] = 0.f;

    const int nst = K / BKT;

    int issueBuf = 0;                          // buffer for next issue
    auto issue = [&]() {
        const uint32_t base = sb + (uint32_t)issueBuf * STGb;
#pragma unroll
        for (int blk = 0; blk < NBLK; blk++) {
#pragma unroll
            for (int i = 0; i < AC; i++)
                cp16(base + blk * A_BLKb + stgOff + (uint32_t)(i * RS * 128),
                     aCur + (size_t)i * RS * K + blk * 32);
#pragma unroll
            for (int i = 0; i < BC; i++)
                cp16(base + A_BYTESb + blk * B_BLKb + stgOff + (uint32_t)(i * RS * 128),
                     bCur + (size_t)i * RS * K + blk * 32);
        }
        cp_commit();
        aCur += BKT; bCur += BKT;
        issueBuf = (issueBuf + 1 == NSTG) ? 0 : issueBuf + 1;
    };

    issue();                                   // stage 0
    issue();                                   // stage 1

    int curBuf = 0;                            // buffer being computed
    for (int s = 0; s < nst; ++s) {
        if (s + 1 < nst) cp_wait<1>();         // stage s landed; s+1 may fly
        else             cp_wait<0>();         // tail: drain everything
        __syncthreads();                       // publish + all consumed prior
        if (s + 2 < nst) issue();              // fill buffer freed at s-1

        const uint32_t stgA = sb + (uint32_t)curBuf * STGb;
        curBuf = (curBuf + 1 == NSTG) ? 0 : curBuf + 1;
#pragma unroll
        for (int kk = 0; kk < NBLK * 4; ++kk) {
            const int blk = kk >> 2;
            const int t   = kk & 3;
            const uint32_t sbA = stgA + (uint32_t)(blk * A_BLKb) + ktA[t];
            const uint32_t sbB = stgA + A_BYTESb + (uint32_t)(blk * B_BLKb) + ktB[t];
            uint32_t af[4][4], bf[4][4];
#pragma unroll
            for (int i = 0; i < 4; ++i)
                ldsm4(af[i][0], af[i][1], af[i][2], af[i][3], sbA + rowA[i]);
#pragma unroll
            for (int j = 0; j < 4; ++j)
                ldsm4(bf[j][0], bf[j][1], bf[j][2], bf[j][3], sbB + rowB[j]);
#pragma unroll
            for (int i = 0; i < 4; ++i)
#pragma unroll
                for (int j = 0; j < 4; ++j) {
                    mma_tf32(acc[i][2 * j],     af[i], bf[j][0], bf[j][1]);
                    mma_tf32(acc[i][2 * j + 1], af[i], bf[j][2], bf[j][3]);
                }
        }
    }

    // ---- epilogue: direct float2 stores --------------------------------------
    const int gr  = lane >> 2;
    const int ctg = lane & 3;
#pragma unroll
    for (int j = 0; j < 8; ++j) {
        const int col = col0 + wn * 64 + j * 8 + 2 * ctg;
        float2 bv = *(const float2*)(Bp + col);
#pragma unroll
        for (int i = 0; i < 4; ++i) {
            const int ra = row0 + wm * 64 + i * 16 + gr;
            const int rb = ra + 8;
            float2 o0, o1;
            o0.x = acc[i][j][0] + bv.x;  o0.y = acc[i][j][1] + bv.y;
            o1.x = acc[i][j][2] + bv.x;  o1.y = acc[i][j][3] + bv.y;
            if (RESID) {
                float2 r0 = *(const float2*)(resid + (size_t)ra * OUTD + col);
                float2 r1 = *(const float2*)(resid + (size_t)rb * OUTD + col);
                o0.x += r0.x; o0.y += r0.y;
                o1.x += r1.x; o1.y += r1.y;
            }
            if (GELU) {
                o0.x = gelu_erf(o0.x); o0.y = gelu_erf(o0.y);
                o1.x = gelu_erf(o1.x); o1.y = gelu_erf(o1.y);
            }
            if (ROUND_OUT) {
                o0.x = to_tf32(o0.x); o0.y = to_tf32(o0.y);
                o1.x = to_tf32(o1.x); o1.y = to_tf32(o1.y);
            }
            *(float2*)(C + (size_t)ra * OUTD + col) = o0;
            *(float2*)(C + (size_t)rb * OUTD + col) = o1;
        }
    }
}

// ---------------- config -------------------------------------------------------
// 128x128x32, 128 threads (4 warps, warp tile 64x64), 3 stages, 2 CTAs/SM
#define SMEM_CFG (3 * (128 * 128 + 128 * 128))    // 98304 bytes per CTA

// ---------------- launch ------------------------------------------------------
extern "C" void kernel_launch(void* const* d_in, const int* in_sizes, int n_in,
                              void* d_out, int out_size)
{
    const float* x      = (const float*)d_in[0];
    const float* ln_g   = (const float*)d_in[1];
    const float* ln_b   = (const float*)d_in[2];
    const float* attn_w = (const float*)d_in[3];
    const float* attn_b = (const float*)d_in[4];
    /* gate_w d_in[5] unused — gating does not affect the output path */
    const float* fc1_w  = (const float*)d_in[6];
    const float* fc1_b  = (const float*)d_in[7];
    const float* fc2_w  = (const float*)d_in[8];
    const float* fc2_b  = (const float*)d_in[9];
    const float* next_w = (const float*)d_in[10];
    const float* next_b = (const float*)d_in[11];
    float* out = (float*)d_out;

    void *p_norm, *p_xattn, *p_h, *p_y, *p_wr;
    cudaGetSymbolAddress(&p_norm,  g_norm);
    cudaGetSymbolAddress(&p_xattn, g_xattn);
    cudaGetSymbolAddress(&p_h,     g_h);
    cudaGetSymbolAddress(&p_y,     g_y);
    cudaGetSymbolAddress(&p_wr,    g_wr);
    float* norm  = (float*)p_norm;
    float* xattn = (float*)p_xattn;
    float* hbuf  = (float*)p_h;
    float* ybuf  = (float*)p_y;
    float* wr    = (float*)p_wr;

    auto kAttn = tc_gemm<128, 128, 32, 128, 2, false, true,  true>;
    auto kFc1  = tc_gemm<128, 128, 32, 128, 2, true,  false, true>;
    auto kFc2  = tc_gemm<128, 128, 32, 128, 2, false, false, true>;
    auto kNext = tc_gemm<128, 128, 32, 128, 2, true,  false, false>;

    cudaFuncSetAttribute(kAttn, cudaFuncAttributeMaxDynamicSharedMemorySize, SMEM_CFG);
    cudaFuncSetAttribute(kFc1,  cudaFuncAttributeMaxDynamicSharedMemorySize, SMEM_CFG);
    cudaFuncSetAttribute(kFc2,  cudaFuncAttributeMaxDynamicSharedMemorySize, SMEM_CFG);
    cudaFuncSetAttribute(kNext, cudaFuncAttributeMaxDynamicSharedMemorySize, SMEM_CFG);

    // 0) pre-round all weights to tf32 (single fused launch)
    {
        const size_t total4 = 2 * (size_t)N4_SMALL + 2 * (size_t)N4_BIG;
        round_all<<<(unsigned)((total4 + 255) / 256), 256>>>(
            (const float4*)attn_w, (const float4*)next_w,
            (const float4*)fc1_w,  (const float4*)fc2_w, (float4*)wr);
    }

    // 1) LayerNorm (tf32-rounded output)
    ln_kernel<<<NTOK / 8, 256>>>(x, ln_g, ln_b, norm);

    // 2) attn linear + residual (output rounded: feeds fc1)
    kAttn<<<dim3(DMODEL / 128, NTOK / 128), 128, SMEM_CFG>>>(
        norm, wr + WR_ATTN, attn_b, x, xattn, DMODEL, DMODEL, 0, 0);

    // 3) fc1 + gelu (per-expert; output rounded: feeds fc2)
    kFc1<<<dim3(HID / 128, NTOK / 128), 128, SMEM_CFG>>>(
        xattn, wr + WR_FC1, fc1_b, nullptr, hbuf, DMODEL, HID,
        (size_t)HID * DMODEL, HID);

    // 4) fc2 (per-expert; output rounded: feeds next)
    kFc2<<<dim3(DMODEL / 128, NTOK / 128), 128, SMEM_CFG>>>(
        hbuf, wr + WR_FC2, fc2_b, nullptr, ybuf, HID, DMODEL,
        (size_t)DMODEL * HID, DMODEL);

    // 5) next linear + gelu (final output, no rounding)
    kNext<<<dim3(DMODEL / 128, NTOK / 128), 128, SMEM_CFG>>>(
        ybuf, wr + WR_NEXT, next_b, nullptr, out, DMODEL, DMODEL, 0, 0);
}

// round 15
// speedup vs baseline: 3.3046x; 1.0995x over previous
#include <cuda_runtime.h>
#include <cuda.h>
#include <cstdint>
#include <cstddef>

// ---------------- problem constants -----------------------------------------
#define NTOK   65536          // B*S
#define DMODEL 512
#define HID    2048
#define NEXP   8

// GEMM tiling: 128x128 tiles, BK=32, 4 warps (64x64 warp tile), 2 CTAs/SM
#define STG    32768          // A(16KB) + B(16KB) per stage
#define NSTG   3
#define MBOFF  (NSTG * STG)   // mbarriers after stage buffers
#define SMEM_TMA (MBOFF + 64)
#define SMEM_CPA (NSTG * STG) // fallback cp.async config

// ---------------- scratch (static device globals; no allocation) ------------
__device__ float g_norm [(size_t)NTOK * DMODEL];
__device__ float g_xattn[(size_t)NTOK * DMODEL];
__device__ float g_h    [(size_t)NTOK * HID];
__device__ float g_y    [(size_t)NTOK * DMODEL];
// pre-rounded (tf32) weights: attn_w | next_w | fc1_w | fc2_w
#define WR_ATTN 0
#define WR_NEXT (512 * 512)
#define WR_FC1  (2 * 512 * 512)
#define WR_FC2  (WR_FC1 + 8 * 2048 * 512)
__device__ float g_wr[(size_t)(2 * 512 * 512 + 2 * 8 * 2048 * 512)];

// ---------------- PTX helpers ------------------------------------------------
__device__ __forceinline__ uint32_t smem_u32(const void* p) {
    uint32_t a;
    asm("{ .reg .u64 t; cvta.to.shared.u64 t, %1; cvt.u32.u64 %0, t; }"
        : "=r"(a) : "l"(p));
    return a;
}
__device__ __forceinline__ float to_tf32(float x) {
    float r;
    asm("cvt.rna.tf32.f32 %0, %1;" : "=f"(r) : "f"(x));
    return r;
}
__device__ __forceinline__ void cp16(uint32_t dst, const void* src) {
    asm volatile("cp.async.cg.shared.global [%0], [%1], 16;"
                 :: "r"(dst), "l"(src) : "memory");
}
__device__ __forceinline__ void cp_commit() {
    asm volatile("cp.async.commit_group;" ::: "memory");
}
template<int N>
__device__ __forceinline__ void cp_wait() {
    asm volatile("cp.async.wait_group %0;" :: "n"(N) : "memory");
}
__device__ __forceinline__ void ldsm4(uint32_t& r0, uint32_t& r1,
                                      uint32_t& r2, uint32_t& r3, uint32_t addr) {
    asm volatile("ldmatrix.sync.aligned.m8n8.x4.shared.b16 {%0,%1,%2,%3}, [%4];"
                 : "=r"(r0), "=r"(r1), "=r"(r2), "=r"(r3) : "r"(addr));
}
__device__ __forceinline__ void mma_tf32(float* d, const uint32_t* a,
                                         uint32_t b0, uint32_t b1) {
    asm volatile(
        "mma.sync.aligned.m16n8k8.row.col.f32.tf32.tf32.f32 "
        "{%0,%1,%2,%3}, {%4,%5,%6,%7}, {%8,%9}, {%0,%1,%2,%3};"
        : "+f"(d[0]), "+f"(d[1]), "+f"(d[2]), "+f"(d[3])
        : "r"(a[0]), "r"(a[1]), "r"(a[2]), "r"(a[3]), "r"(b0), "r"(b1));
}
__device__ __forceinline__ float gelu_erf(float x) {
    return 0.5f * x * (1.0f + erff(x * 0.70710678118654752f));
}
__device__ __forceinline__ uint32_t swz(uint32_t off) {
    return off ^ ((off >> 3) & 0x70);
}
#define MBARRIER_INIT(mbar, cnt) \
    asm volatile("mbarrier.init.shared.b64 [%0], %1;" \
                 :: "r"((uint32_t)(mbar)), "r"((uint32_t)(cnt)) : "memory")
#define MBARRIER_EXPECT_TX(mbar, bytes) \
    asm volatile("mbarrier.arrive.expect_tx.shared.b64 _, [%0], %1;" \
                 :: "r"((uint32_t)(mbar)), "r"((uint32_t)(bytes)) : "memory")
#define MBARRIER_WAIT_PARITY(mbar_smem_addr, phase_parity) do { \
    uint32_t _mbar = (uint32_t)(mbar_smem_addr); \
    uint32_t _parity = (uint32_t)(phase_parity); \
    uint32_t _done; \
    asm volatile( \
        "{\n\t.reg .pred p;\n\t" \
        "mbarrier.try_wait.parity.acquire.cta.shared::cta.b64 p, [%1], %2;\n\t" \
        "selp.b32 %0, 1, 0, p;\n\t}" \
        : "=r"(_done) : "r"(_mbar), "r"(_parity) : "memory"); \
    if (!_done) { \
        asm volatile( \
            "{\n\t.reg .pred P1;\n\t" \
            "WAIT_LOOP_%=:\n\t" \
            "mbarrier.try_wait.parity.acquire.cta.shared::cta.b64 P1, [%0], %1, 0x989680;\n\t" \
            "@P1 bra.uni WAIT_DONE_%=;\n\t" \
            "bra.uni WAIT_LOOP_%=;\n\t" \
            "WAIT_DONE_%=:\n\t}" \
            :: "r"(_mbar), "r"(_parity) : "memory"); \
    } \
} while (0)
__device__ __forceinline__ void tma3d(uint32_t dst, const CUtensorMap* map,
                                      int x, int y, int z, uint32_t mbar) {
    asm volatile(
        "cp.async.bulk.tensor.3d.shared::cta.global.tile.mbarrier::complete_tx::bytes "
        "[%0], [%1, {%2, %3, %4}], [%5];"
        :: "r"(dst), "l"(map), "r"(x), "r"(y), "r"(z), "r"(mbar) : "memory");
}

// ---------------- fused weight pre-round (fp32 -> tf32 bits), 1 launch -------
#define N4_SMALL (512 * 512 / 4)
#define N4_BIG   (8 * 2048 * 512 / 4)
__global__ void __launch_bounds__(256) round_all(
    const float4* __restrict__ s0, const float4* __restrict__ s1,
    const float4* __restrict__ s2, const float4* __restrict__ s3,
    float4* __restrict__ dst)
{
    size_t i = (size_t)blockIdx.x * 256 + threadIdx.x;
    const float4* src;
    size_t off;
    if (i < N4_SMALL)                       { src = s0; off = i; }
    else if (i < 2 * N4_SMALL)              { src = s1; off = i - N4_SMALL; }
    else if (i < 2 * N4_SMALL + N4_BIG)     { src = s2; off = i - 2 * N4_SMALL; }
    else if (i < 2 * N4_SMALL + 2 * N4_BIG) { src = s3; off = i - 2 * N4_SMALL - N4_BIG; }
    else return;
    float4 v = src[off];
    v.x = to_tf32(v.x); v.y = to_tf32(v.y);
    v.z = to_tf32(v.z); v.w = to_tf32(v.w);
    dst[i] = v;
}

// ---------------- LayerNorm (warp per token, tf32-rounded output) ------------
__global__ void __launch_bounds__(256) ln_kernel(
    const float* __restrict__ x, const float* __restrict__ g,
    const float* __restrict__ b, float* __restrict__ out)
{
    const int warp = threadIdx.x >> 5;
    const int lane = threadIdx.x & 31;
    const int token = blockIdx.x * 8 + warp;
    const float* row = x + (size_t)token * DMODEL;

    float4 v[4];
    float s = 0.f, ss = 0.f;
#pragma unroll
    for (int q = 0; q < 4; q++) {
        v[q] = *(const float4*)(row + (size_t)(q * 32 + lane) * 4);
        s  += v[q].x + v[q].y + v[q].z + v[q].w;
        ss  = fmaf(v[q].x, v[q].x, ss);
        ss  = fmaf(v[q].y, v[q].y, ss);
        ss  = fmaf(v[q].z, v[q].z, ss);
        ss  = fmaf(v[q].w, v[q].w, ss);
    }
#pragma unroll
    for (int off = 16; off > 0; off >>= 1) {
        s  += __shfl_xor_sync(0xffffffffu, s,  off);
        ss += __shfl_xor_sync(0xffffffffu, ss, off);
    }
    const float mu  = s * (1.0f / DMODEL);
    const float var = ss * (1.0f / DMODEL) - mu * mu;
    const float rs  = rsqrtf(var + 1e-5f);

    float* orow = out + (size_t)token * DMODEL;
#pragma unroll
    for (int q = 0; q < 4; q++) {
        const int c = (q * 32 + lane) * 4;
        float4 gg = *(const float4*)(g + c);
        float4 bb = *(const float4*)(b + c);
        float4 o;
        o.x = to_tf32((v[q].x - mu) * rs * gg.x + bb.x);
        o.y = to_tf32((v[q].y - mu) * rs * gg.y + bb.y);
        o.z = to_tf32((v[q].z - mu) * rs * gg.z + bb.z);
        o.w = to_tf32((v[q].w - mu) * rs * gg.w + bb.w);
        *(float4*)(orow + c) = o;
    }
}

// ---------------- shared epilogue --------------------------------------------
template<bool GELU, bool RESID, bool ROUND_OUT>
__device__ __forceinline__ void epilogue(
    float acc[4][8][4], const float* Bp, const float* resid, float* C,
    int row0, int col0, int OUTD, int wm, int wn, int lane)
{
    const int gr  = lane >> 2;
    const int ctg = lane & 3;
#pragma unroll
    for (int j = 0; j < 8; ++j) {
        const int col = col0 + wn * 64 + j * 8 + 2 * ctg;
        float2 bv = *(const float2*)(Bp + col);
#pragma unroll
        for (int i = 0; i < 4; ++i) {
            const int ra = row0 + wm * 64 + i * 16 + gr;
            const int rb = ra + 8;
            float2 o0, o1;
            o0.x = acc[i][j][0] + bv.x;  o0.y = acc[i][j][1] + bv.y;
            o1.x = acc[i][j][2] + bv.x;  o1.y = acc[i][j][3] + bv.y;
            if (RESID) {
                float2 r0 = *(const float2*)(resid + (size_t)ra * OUTD + col);
                float2 r1 = *(const float2*)(resid + (size_t)rb * OUTD + col);
                o0.x += r0.x; o0.y += r0.y;
                o1.x += r1.x; o1.y += r1.y;
            }
            if (GELU) {
                o0.x = gelu_erf(o0.x); o0.y = gelu_erf(o0.y);
                o1.x = gelu_erf(o1.x); o1.y = gelu_erf(o1.y);
            }
            if (ROUND_OUT) {
                o0.x = to_tf32(o0.x); o0.y = to_tf32(o0.y);
                o1.x = to_tf32(o1.x); o1.y = to_tf32(o1.y);
            }
            *(float2*)(C + (size_t)ra * OUTD + col) = o0;
            *(float2*)(C + (size_t)rb * OUTD + col) = o1;
        }
    }
}

// ---------------- TMA-fed tf32 GEMM: 128x128x32, 4 warps, 2 CTAs/SM ----------
template<bool GELU, bool RESID, bool ROUND_OUT>
__global__ void __launch_bounds__(128, 2)
tc_gemm_tma(const __grid_constant__ CUtensorMap mapA,
            const __grid_constant__ CUtensorMap mapB,
            const float* __restrict__ bias, const float* __restrict__ resid,
            float* __restrict__ C, int K, int OUTD, int b_estride)
{
    extern __shared__ char smem[];
    const uint32_t sb = smem_u32(smem);
    const int tid  = threadIdx.x;
    const int wid  = tid >> 5;
    const int lane = tid & 31;
    const int row0 = blockIdx.y * 128;
    const int col0 = blockIdx.x * 128;

    const int e = (row0 >> 12) & 7;            // expert id (4096-token chunks)
    const int eTma = b_estride ? e : 0;
    const float* Bp = bias + (b_estride ? e * b_estride : 0);

    const int wm = wid & 1;
    const int wn = wid >> 1;

    // ldmatrix lane-derived components + hoisted swizzle
    const int aRow  = (lane & 7) + ((lane >> 3) & 1) * 8;
    const int aBSel = (lane >> 4) * 16;
    const int bRow  = (lane & 7) + ((lane >> 4) & 1) * 8;
    const int bBSel = ((lane >> 3) & 1) * 16;
    const uint32_t xA = (uint32_t)((aRow & 7) << 4);
    const uint32_t xB = (uint32_t)((bRow & 7) << 4);
    uint32_t rowA[4], rowB[4], ktA[4], ktB[4];
#pragma unroll
    for (int i = 0; i < 4; i++)
        rowA[i] = (uint32_t)((wm * 64 + i * 16 + aRow) * 128);
#pragma unroll
    for (int j = 0; j < 4; j++)
        rowB[j] = (uint32_t)((wn * 64 + j * 16 + bRow) * 128);
#pragma unroll
    for (int t = 0; t < 4; t++) {
        ktA[t] = (uint32_t)(t * 32 + aBSel) ^ xA;
        ktB[t] = (uint32_t)(t * 32 + bBSel) ^ xB;
    }

    const uint32_t mb = sb + MBOFF;
    if (tid == 0) {
#pragma unroll
        for (int i = 0; i < NSTG; i++) MBARRIER_INIT(mb + 8 * i, 1);
    }
    __syncthreads();

    float acc[4][8][4];
#pragma unroll
    for (int i = 0; i < 4; i++)
#pragma unroll
        for (int j = 0; j < 8; j++)
#pragma unroll
            for (int q = 0; q < 4; q++) acc[i][j][q] = 0.f;

    const int nst = K / 32;

    auto issue = [&](int s) {                  // single-thread
        const int buf = s % NSTG;
        const uint32_t m = mb + 8 * buf;
        MBARRIER_EXPECT_TX(m, STG);
        const uint32_t dstA = sb + (uint32_t)buf * STG;
        tma3d(dstA,         &mapA, s * 32, row0, 0,    m);
        tma3d(dstA + 16384, &mapB, s * 32, col0, eTma, m);
    };

    if (tid == 0) { issue(0); issue(1); }

    for (int s = 0; s < nst; ++s) {
        if (tid == 0 && s + 2 < nst) issue(s + 2);   // buf freed at end of s-1
        MBARRIER_WAIT_PARITY(mb + 8 * (s % NSTG), (s / NSTG) & 1);

        const uint32_t stgA = sb + (uint32_t)(s % NSTG) * STG;
#pragma unroll
        for (int kk = 0; kk < 4; ++kk) {
            const uint32_t sbA = stgA + ktA[kk];
            const uint32_t sbB = stgA + 16384 + ktB[kk];
            uint32_t af[4][4], bf[4][4];
#pragma unroll
            for (int i = 0; i < 4; ++i)
                ldsm4(af[i][0], af[i][1], af[i][2], af[i][3], sbA + rowA[i]);
#pragma unroll
            for (int j = 0; j < 4; ++j)
                ldsm4(bf[j][0], bf[j][1], bf[j][2], bf[j][3], sbB + rowB[j]);
#pragma unroll
            for (int i = 0; i < 4; ++i)
#pragma unroll
                for (int j = 0; j < 4; ++j) {
                    mma_tf32(acc[i][2 * j],     af[i], bf[j][0], bf[j][1]);
                    mma_tf32(acc[i][2 * j + 1], af[i], bf[j][2], bf[j][3]);
                }
        }
        __syncthreads();                        // all warps done with buf s
    }

    epilogue<GELU, RESID, ROUND_OUT>(acc, Bp, resid, C, row0, col0, OUTD, wm, wn, lane);
}

// ---------------- fallback: cp.async tf32 GEMM (R13, proven 1688us) ----------
template<bool GELU, bool RESID, bool ROUND_OUT>
__global__ void __launch_bounds__(128, 2)
tc_gemm(const float* __restrict__ A, const float* __restrict__ W,
        const float* __restrict__ bias, const float* __restrict__ resid,
        float* __restrict__ C, int K, int OUTD,
        size_t w_estride, int b_estride)
{
    extern __shared__ char smem[];
    const uint32_t sb = smem_u32(smem);
    const int tid  = threadIdx.x;
    const int wid  = tid >> 5;
    const int lane = tid & 31;
    const int row0 = blockIdx.y * 128;
    const int col0 = blockIdx.x * 128;

    const int e = (row0 >> 12) & 7;
    const float* Wp = W + (w_estride ? (size_t)e * w_estride : 0);
    const float* Bp = bias + (b_estride ? e * b_estride : 0);

    const int wm = wid & 1;
    const int wn = wid >> 1;

    const int aRow  = (lane & 7) + ((lane >> 3) & 1) * 8;
    const int aBSel = (lane >> 4) * 16;
    const int bRow  = (lane & 7) + ((lane >> 4) & 1) * 8;
    const int bBSel = ((lane >> 3) & 1) * 16;
    const uint32_t xA = (uint32_t)((aRow & 7) << 4);
    const uint32_t xB = (uint32_t)((bRow & 7) << 4);
    uint32_t rowA[4], rowB[4], ktA[4], ktB[4];
#pragma unroll
    for (int i = 0; i < 4; i++)
        rowA[i] = (uint32_t)((wm * 64 + i * 16 + aRow) * 128);
#pragma unroll
    for (int j = 0; j < 4; j++)
        rowB[j] = (uint32_t)((wn * 64 + j * 16 + bRow) * 128);
#pragma unroll
    for (int t = 0; t < 4; t++) {
        ktA[t] = (uint32_t)(t * 32 + aBSel) ^ xA;
        ktB[t] = (uint32_t)(t * 32 + bBSel) ^ xB;
    }

    const int sr = tid >> 3;
    const int sq = tid & 7;
    const uint32_t stgOff = swz((uint32_t)(sr * 128 + sq * 16));

    const float* aCur = A  + (size_t)(row0 + sr) * K + sq * 4;
    const float* bCur = Wp + (size_t)(col0 + sr) * K + sq * 4;

    float acc[4][8][4];
#pragma unroll
    for (int i = 0; i < 4; i++)
#pragma unroll
        for (int j = 0; j < 8; j++)
#pragma unroll
            for (int q = 0; q < 4; q++) acc[i][j][q] = 0.f;

    const int nst = K / 32;
    int issueBuf = 0;
    auto issue = [&]() {
        const uint32_t base = sb + (uint32_t)issueBuf * STG;
#pragma unroll
        for (int i = 0; i < 8; i++)
            cp16(base + stgOff + (uint32_t)(i * 16 * 128),
                 aCur + (size_t)i * 16 * K);
#pragma unroll
        for (int i = 0; i < 8; i++)
            cp16(base + 16384 + stgOff + (uint32_t)(i * 16 * 128),
                 bCur + (size_t)i * 16 * K);
        cp_commit();
        aCur += 32; bCur += 32;
        issueBuf = (issueBuf + 1 == NSTG) ? 0 : issueBuf + 1;
    };

    issue(); issue();

    int curBuf = 0;
    for (int s = 0; s < nst; ++s) {
        if (s + 1 < nst) cp_wait<1>();
        else             cp_wait<0>();
        __syncthreads();
        if (s + 2 < nst) issue();

        const uint32_t stgA = sb + (uint32_t)curBuf * STG;
        curBuf = (curBuf + 1 == NSTG) ? 0 : curBuf + 1;
#pragma unroll
        for (int kk = 0; kk < 4; ++kk) {
            const uint32_t sbA = stgA + ktA[kk];
            const uint32_t sbB = stgA + 16384 + ktB[kk];
            uint32_t af[4][4], bf[4][4];
#pragma unroll
            for (int i = 0; i < 4; ++i)
                ldsm4(af[i][0], af[i][1], af[i][2], af[i][3], sbA + rowA[i]);
#pragma unroll
            for (int j = 0; j < 4; ++j)
                ldsm4(bf[j][0], bf[j][1], bf[j][2], bf[j][3], sbB + rowB[j]);
#pragma unroll
            for (int i = 0; i < 4; ++i)
#pragma unroll
                for (int j = 0; j < 4; ++j) {
                    mma_tf32(acc[i][2 * j],     af[i], bf[j][0], bf[j][1]);
                    mma_tf32(acc[i][2 * j + 1], af[i], bf[j][2], bf[j][3]);
                }
        }
    }

    epilogue<GELU, RESID, ROUND_OUT>(acc, Bp, resid, C, row0, col0, OUTD, wm, wn, lane);
}

// ---------------- host: tensor-map encoding via runtime entry point ----------
typedef CUresult (CUDAAPI *tmap_encode_t)(
    CUtensorMap*, CUtensorMapDataType, cuuint32_t, void*,
    const cuuint64_t*, const cuuint64_t*, const cuuint32_t*, const cuuint32_t*,
    CUtensorMapInterleave, CUtensorMapSwizzle, CUtensorMapL2promotion,
    CUtensorMapFloatOOBfill);

static bool encode3d(tmap_encode_t fn, CUtensorMap* m, void* base,
                     uint64_t d0, uint64_t d1, uint64_t d2)
{
    cuuint64_t dims[3]    = {d0, d1, d2};
    cuuint64_t strides[2] = {d0 * 4, d0 * d1 * 4};
    cuuint32_t box[3]     = {32, 128, 1};
    cuuint32_t estr[3]    = {1, 1, 1};
    return fn(m, CU_TENSOR_MAP_DATA_TYPE_FLOAT32, 3, base, dims, strides, box,
              estr, CU_TENSOR_MAP_INTERLEAVE_NONE, CU_TENSOR_MAP_SWIZZLE_128B,
              CU_TENSOR_MAP_L2_PROMOTION_L2_128B,
              CU_TENSOR_MAP_FLOAT_OOB_FILL_NONE) == CUDA_SUCCESS;
}

// ---------------- launch ------------------------------------------------------
extern "C" void kernel_launch(void* const* d_in, const int* in_sizes, int n_in,
                              void* d_out, int out_size)
{
    const float* x      = (const float*)d_in[0];
    const float* ln_g   = (const float*)d_in[1];
    const float* ln_b   = (const float*)d_in[2];
    const float* attn_w = (const float*)d_in[3];
    const float* attn_b = (const float*)d_in[4];
    /* gate_w d_in[5] unused */
    const float* fc1_w  = (const float*)d_in[6];
    const float* fc1_b  = (const float*)d_in[7];
    const float* fc2_w  = (const float*)d_in[8];
    const float* fc2_b  = (const float*)d_in[9];
    const float* next_w = (const float*)d_in[10];
    const float* next_b = (const float*)d_in[11];
    float* out = (float*)d_out;

    void *p_norm, *p_xattn, *p_h, *p_y, *p_wr;
    cudaGetSymbolAddress(&p_norm,  g_norm);
    cudaGetSymbolAddress(&p_xattn, g_xattn);
    cudaGetSymbolAddress(&p_h,     g_h);
    cudaGetSymbolAddress(&p_y,     g_y);
    cudaGetSymbolAddress(&p_wr,    g_wr);
    float* norm  = (float*)p_norm;
    float* xattn = (float*)p_xattn;
    float* hbuf  = (float*)p_h;
    float* ybuf  = (float*)p_y;
    float* wr    = (float*)p_wr;

    // 0) pre-round all weights to tf32 (single fused launch)
    {
        const size_t total4 = 2 * (size_t)N4_SMALL + 2 * (size_t)N4_BIG;
        round_all<<<(unsigned)((total4 + 255) / 256), 256>>>(
            (const float4*)attn_w, (const float4*)next_w,
            (const float4*)fc1_w,  (const float4*)fc2_w, (float4*)wr);
    }

    // 1) LayerNorm (tf32-rounded output)
    ln_kernel<<<NTOK / 8, 256>>>(x, ln_g, ln_b, norm);

    // try TMA path: encode 8 tensor maps
    tmap_encode_t enc = nullptr;
    {
        void* fp = nullptr;
        cudaDriverEntryPointQueryResult qr;
#if CUDART_VERSION >= 12050
        cudaGetDriverEntryPointByVersion("cuTensorMapEncodeTiled", &fp, 12000,
                                         cudaEnableDefault, &qr);
#else
        cudaGetDriverEntryPoint("cuTensorMapEncodeTiled", &fp,
                                cudaEnableDefault, &qr);
#endif
        if (fp && qr == cudaDriverEntryPointSuccess) enc = (tmap_encode_t)fp;
    }

    CUtensorMap mAttnA, mAttnB, mFc1A, mFc1B, mFc2A, mFc2B, mNextA, mNextB;
    bool tmaOK = (enc != nullptr);
    if (tmaOK) {
        tmaOK = tmaOK && encode3d(enc, &mAttnA, norm,          DMODEL, NTOK,  1);
        tmaOK = tmaOK && encode3d(enc, &mAttnB, wr + WR_ATTN,  DMODEL, DMODEL, 1);
        tmaOK = tmaOK && encode3d(enc, &mFc1A,  xattn,         DMODEL, NTOK,  1);
        tmaOK = tmaOK && encode3d(enc, &mFc1B,  wr + WR_FC1,   DMODEL, HID,   NEXP);
        tmaOK = tmaOK && encode3d(enc, &mFc2A,  hbuf,          HID,    NTOK,  1);
        tmaOK = tmaOK && encode3d(enc, &mFc2B,  wr + WR_FC2,   HID,    DMODEL, NEXP);
        tmaOK = tmaOK && encode3d(enc, &mNextA, ybuf,          DMODEL, NTOK,  1);
        tmaOK = tmaOK && encode3d(enc, &mNextB, wr + WR_NEXT,  DMODEL, DMODEL, 1);
    }

    if (tmaOK) {
        auto kA = tc_gemm_tma<false, true,  true>;
        auto k1 = tc_gemm_tma<true,  false, true>;
        auto k2 = tc_gemm_tma<false, false, true>;
        auto kN = tc_gemm_tma<true,  false, false>;
        cudaFuncSetAttribute(kA, cudaFuncAttributeMaxDynamicSharedMemorySize, SMEM_TMA);
        cudaFuncSetAttribute(k1, cudaFuncAttributeMaxDynamicSharedMemorySize, SMEM_TMA);
        cudaFuncSetAttribute(k2, cudaFuncAttributeMaxDynamicSharedMemorySize, SMEM_TMA);
        cudaFuncSetAttribute(kN, cudaFuncAttributeMaxDynamicSharedMemorySize, SMEM_TMA);

        kA<<<dim3(DMODEL / 128, NTOK / 128), 128, SMEM_TMA>>>(
            mAttnA, mAttnB, attn_b, x, xattn, DMODEL, DMODEL, 0);
        k1<<<dim3(HID / 128, NTOK / 128), 128, SMEM_TMA>>>(
            mFc1A, mFc1B, fc1_b, nullptr, hbuf, DMODEL, HID, HID);
        k2<<<dim3(DMODEL / 128, NTOK / 128), 128, SMEM_TMA>>>(
            mFc2A, mFc2B, fc2_b, nullptr, ybuf, HID, DMODEL, DMODEL);
        kN<<<dim3(DMODEL / 128, NTOK / 128), 128, SMEM_TMA>>>(
            mNextA, mNextB, next_b, nullptr, out, DMODEL, DMODEL, 0);
    } else {
        // fallback: proven cp.async path (R13)
        auto kA = tc_gemm<false, true,  true>;
        auto k1 = tc_gemm<true,  false, true>;
        auto k2 = tc_gemm<false, false, true>;
        auto kN = tc_gemm<true,  false, false>;
        cudaFuncSetAttribute(kA, cudaFuncAttributeMaxDynamicSharedMemorySize, SMEM_CPA);
        cudaFuncSetAttribute(k1, cudaFuncAttributeMaxDynamicSharedMemorySize, SMEM_CPA);
        cudaFuncSetAttribute(k2, cudaFuncAttributeMaxDynamicSharedMemorySize, SMEM_CPA);
        cudaFuncSetAttribute(kN, cudaFuncAttributeMaxDynamicSharedMemorySize, SMEM_CPA);

        kA<<<dim3(DMODEL / 128, NTOK / 128), 128, SMEM_CPA>>>(
            norm, wr + WR_ATTN, attn_b, x, xattn, DMODEL, DMODEL, 0, 0);
        k1<<<dim3(HID / 128, NTOK / 128), 128, SMEM_CPA>>>(
            xattn, wr + WR_FC1, fc1_b, nullptr, hbuf, DMODEL, HID,
            (size_t)HID * DMODEL, HID);
        k2<<<dim3(DMODEL / 128, NTOK / 128), 128, SMEM_CPA>>>(
            hbuf, wr + WR_FC2, fc2_b, nullptr, ybuf, HID, DMODEL,
            (size_t)DMODEL * HID, DMODEL);
        kN<<<dim3(DMODEL / 128, NTOK / 128), 128, SMEM_CPA>>>(
            ybuf, wr + WR_NEXT, next_b, nullptr, out, DMODEL, DMODEL, 0, 0);
    }
}

// round 16
// speedup vs baseline: 3.3608x; 1.0170x over previous
#include <cuda_runtime.h>
#include <cuda.h>
#include <cstdint>
#include <cstddef>

// ---------------- problem constants -----------------------------------------
#define NTOK   65536          // B*S
#define DMODEL 512
#define HID    2048
#define NEXP   8

// GEMM tiling: 128x128 tiles, BK=32, 4 warps (64x64 warp tile), 2 CTAs/SM
#define STG    32768          // A(16KB) + B(16KB) per stage
#define NSTG   3
#define MBOFF  (NSTG * STG)   // mbarriers after stage buffers
#define SMEM_TMA (MBOFF + 64)
#define SMEM_CPA (NSTG * STG) // fallback cp.async config

// ---------------- scratch (static device globals; no allocation) ------------
__device__ float g_norm [(size_t)NTOK * DMODEL];
__device__ float g_xattn[(size_t)NTOK * DMODEL];
__device__ float g_h    [(size_t)NTOK * HID];
__device__ float g_y    [(size_t)NTOK * DMODEL];
// pre-rounded (tf32) weights: attn_w | next_w | fc1_w | fc2_w
#define WR_ATTN 0
#define WR_NEXT (512 * 512)
#define WR_FC1  (2 * 512 * 512)
#define WR_FC2  (WR_FC1 + 8 * 2048 * 512)
__device__ float g_wr[(size_t)(2 * 512 * 512 + 2 * 8 * 2048 * 512)];

// ---------------- PTX helpers ------------------------------------------------
__device__ __forceinline__ uint32_t smem_u32(const void* p) {
    uint32_t a;
    asm("{ .reg .u64 t; cvta.to.shared.u64 t, %1; cvt.u32.u64 %0, t; }"
        : "=r"(a) : "l"(p));
    return a;
}
__device__ __forceinline__ float to_tf32(float x) {
    float r;
    asm("cvt.rna.tf32.f32 %0, %1;" : "=f"(r) : "f"(x));
    return r;
}
__device__ __forceinline__ void cp16(uint32_t dst, const void* src) {
    asm volatile("cp.async.cg.shared.global [%0], [%1], 16;"
                 :: "r"(dst), "l"(src) : "memory");
}
__device__ __forceinline__ void cp_commit() {
    asm volatile("cp.async.commit_group;" ::: "memory");
}
template<int N>
__device__ __forceinline__ void cp_wait() {
    asm volatile("cp.async.wait_group %0;" :: "n"(N) : "memory");
}
__device__ __forceinline__ void ldsm4(uint32_t& r0, uint32_t& r1,
                                      uint32_t& r2, uint32_t& r3, uint32_t addr) {
    asm volatile("ldmatrix.sync.aligned.m8n8.x4.shared.b16 {%0,%1,%2,%3}, [%4];"
                 : "=r"(r0), "=r"(r1), "=r"(r2), "=r"(r3) : "r"(addr));
}
__device__ __forceinline__ void mma_tf32(float* d, const uint32_t* a,
                                         uint32_t b0, uint32_t b1) {
    asm volatile(
        "mma.sync.aligned.m16n8k8.row.col.f32.tf32.tf32.f32 "
        "{%0,%1,%2,%3}, {%4,%5,%6,%7}, {%8,%9}, {%0,%1,%2,%3};"
        : "+f"(d[0]), "+f"(d[1]), "+f"(d[2]), "+f"(d[3])
        : "r"(a[0]), "r"(a[1]), "r"(a[2]), "r"(a[3]), "r"(b0), "r"(b1));
}
__device__ __forceinline__ float gelu_erf(float x) {
    return 0.5f * x * (1.0f + erff(x * 0.70710678118654752f));
}
__device__ __forceinline__ uint32_t swz(uint32_t off) {
    return off ^ ((off >> 3) & 0x70);
}
#define MBARRIER_INIT(mbar, cnt) \
    asm volatile("mbarrier.init.shared.b64 [%0], %1;" \
                 :: "r"((uint32_t)(mbar)), "r"((uint32_t)(cnt)) : "memory")
#define MBARRIER_EXPECT_TX(mbar, bytes) \
    asm volatile("mbarrier.arrive.expect_tx.shared.b64 _, [%0], %1;" \
                 :: "r"((uint32_t)(mbar)), "r"((uint32_t)(bytes)) : "memory")
#define MBARRIER_ARRIVE(mbar) \
    asm volatile("mbarrier.arrive.shared.b64 _, [%0];" \
                 :: "r"((uint32_t)(mbar)) : "memory")
#define MBARRIER_WAIT_PARITY(mbar_smem_addr, phase_parity) do { \
    uint32_t _mbar = (uint32_t)(mbar_smem_addr); \
    uint32_t _parity = (uint32_t)(phase_parity); \
    uint32_t _done; \
    asm volatile( \
        "{\n\t.reg .pred p;\n\t" \
        "mbarrier.try_wait.parity.acquire.cta.shared::cta.b64 p, [%1], %2;\n\t" \
        "selp.b32 %0, 1, 0, p;\n\t}" \
        : "=r"(_done) : "r"(_mbar), "r"(_parity) : "memory"); \
    if (!_done) { \
        asm volatile( \
            "{\n\t.reg .pred P1;\n\t" \
            "WAIT_LOOP_%=:\n\t" \
            "mbarrier.try_wait.parity.acquire.cta.shared::cta.b64 P1, [%0], %1, 0x989680;\n\t" \
            "@P1 bra.uni WAIT_DONE_%=;\n\t" \
            "bra.uni WAIT_LOOP_%=;\n\t" \
            "WAIT_DONE_%=:\n\t}" \
            :: "r"(_mbar), "r"(_parity) : "memory"); \
    } \
} while (0)
__device__ __forceinline__ void tma3d(uint32_t dst, const CUtensorMap* map,
                                      int x, int y, int z, uint32_t mbar) {
    asm volatile(
        "cp.async.bulk.tensor.3d.shared::cta.global.tile.mbarrier::complete_tx::bytes "
        "[%0], [%1, {%2, %3, %4}], [%5];"
        :: "r"(dst), "l"(map), "r"(x), "r"(y), "r"(z), "r"(mbar) : "memory");
}

// ---------------- fused weight pre-round (fp32 -> tf32 bits), 1 launch -------
#define N4_SMALL (512 * 512 / 4)
#define N4_BIG   (8 * 2048 * 512 / 4)
#define N4_TOTAL (2 * N4_SMALL + 2 * N4_BIG)
__global__ void __launch_bounds__(256) round_all(
    const float4* __restrict__ s0, const float4* __restrict__ s1,
    const float4* __restrict__ s2, const float4* __restrict__ s3,
    float4* __restrict__ dst)
{
    const size_t base = (size_t)blockIdx.x * 1024 + threadIdx.x;
#pragma unroll
    for (int k = 0; k < 4; k++) {
        size_t i = base + (size_t)k * 256;
        if (i >= (size_t)N4_TOTAL) continue;
        const float4* src;
        size_t off;
        if (i < N4_SMALL)                       { src = s0; off = i; }
        else if (i < 2 * N4_SMALL)              { src = s1; off = i - N4_SMALL; }
        else if (i < 2 * N4_SMALL + N4_BIG)     { src = s2; off = i - 2 * N4_SMALL; }
        else                                    { src = s3; off = i - 2 * N4_SMALL - N4_BIG; }
        float4 v = src[off];
        v.x = to_tf32(v.x); v.y = to_tf32(v.y);
        v.z = to_tf32(v.z); v.w = to_tf32(v.w);
        dst[i] = v;
    }
}

// ---------------- LayerNorm (warp per token, tf32-rounded output) ------------
__global__ void __launch_bounds__(256) ln_kernel(
    const float* __restrict__ x, const float* __restrict__ g,
    const float* __restrict__ b, float* __restrict__ out)
{
    const int warp = threadIdx.x >> 5;
    const int lane = threadIdx.x & 31;
    const int token = blockIdx.x * 8 + warp;
    const float* row = x + (size_t)token * DMODEL;

    float4 v[4];
    float s = 0.f, ss = 0.f;
#pragma unroll
    for (int q = 0; q < 4; q++) {
        v[q] = *(const float4*)(row + (size_t)(q * 32 + lane) * 4);
        s  += v[q].x + v[q].y + v[q].z + v[q].w;
        ss  = fmaf(v[q].x, v[q].x, ss);
        ss  = fmaf(v[q].y, v[q].y, ss);
        ss  = fmaf(v[q].z, v[q].z, ss);
        ss  = fmaf(v[q].w, v[q].w, ss);
    }
#pragma unroll
    for (int off = 16; off > 0; off >>= 1) {
        s  += __shfl_xor_sync(0xffffffffu, s,  off);
        ss += __shfl_xor_sync(0xffffffffu, ss, off);
    }
    const float mu  = s * (1.0f / DMODEL);
    const float var = ss * (1.0f / DMODEL) - mu * mu;
    const float rs  = rsqrtf(var + 1e-5f);

    float* orow = out + (size_t)token * DMODEL;
#pragma unroll
    for (int q = 0; q < 4; q++) {
        const int c = (q * 32 + lane) * 4;
        float4 gg = *(const float4*)(g + c);
        float4 bb = *(const float4*)(b + c);
        float4 o;
        o.x = to_tf32((v[q].x - mu) * rs * gg.x + bb.x);
        o.y = to_tf32((v[q].y - mu) * rs * gg.y + bb.y);
        o.z = to_tf32((v[q].z - mu) * rs * gg.z + bb.z);
        o.w = to_tf32((v[q].w - mu) * rs * gg.w + bb.w);
        *(float4*)(orow + c) = o;
    }
}

// ---------------- shared epilogue --------------------------------------------
template<bool GELU, bool RESID, bool ROUND_OUT>
__device__ __forceinline__ void epilogue(
    float acc[4][8][4], const float* Bp, const float* resid, float* C,
    int row0, int col0, int OUTD, int wm, int wn, int lane)
{
    const int gr  = lane >> 2;
    const int ctg = lane & 3;
#pragma unroll
    for (int j = 0; j < 8; ++j) {
        const int col = col0 + wn * 64 + j * 8 + 2 * ctg;
        float2 bv = *(const float2*)(Bp + col);
#pragma unroll
        for (int i = 0; i < 4; ++i) {
            const int ra = row0 + wm * 64 + i * 16 + gr;
            const int rb = ra + 8;
            float2 o0, o1;
            o0.x = acc[i][j][0] + bv.x;  o0.y = acc[i][j][1] + bv.y;
            o1.x = acc[i][j][2] + bv.x;  o1.y = acc[i][j][3] + bv.y;
            if (RESID) {
                float2 r0 = *(const float2*)(resid + (size_t)ra * OUTD + col);
                float2 r1 = *(const float2*)(resid + (size_t)rb * OUTD + col);
                o0.x += r0.x; o0.y += r0.y;
                o1.x += r1.x; o1.y += r1.y;
            }
            if (GELU) {
                o0.x = gelu_erf(o0.x); o0.y = gelu_erf(o0.y);
                o1.x = gelu_erf(o1.x); o1.y = gelu_erf(o1.y);
            }
            if (ROUND_OUT) {
                o0.x = to_tf32(o0.x); o0.y = to_tf32(o0.y);
                o1.x = to_tf32(o1.x); o1.y = to_tf32(o1.y);
            }
            *(float2*)(C + (size_t)ra * OUTD + col) = o0;
            *(float2*)(C + (size_t)rb * OUTD + col) = o1;
        }
    }
}

// ---------------- TMA-fed tf32 GEMM: full/empty mbarrier pipeline ------------
// 128x128x32, 4 warps (64x64 warp tile), 2 CTAs/SM, NO per-stage syncthreads.
// full[b]: TMA complete_tx (count 1). empty[b]: 4 warp arrivals.
template<bool GELU, bool RESID, bool ROUND_OUT>
__global__ void __launch_bounds__(128, 2)
tc_gemm_tma(const __grid_constant__ CUtensorMap mapA,
            const __grid_constant__ CUtensorMap mapB,
            const float* __restrict__ bias, const float* __restrict__ resid,
            float* __restrict__ C, int K, int OUTD, int b_estride)
{
    extern __shared__ char smem[];
    const uint32_t sb = smem_u32(smem);
    const int tid  = threadIdx.x;
    const int wid  = tid >> 5;
    const int lane = tid & 31;
    const int row0 = blockIdx.y * 128;
    const int col0 = blockIdx.x * 128;

    const int e = (row0 >> 12) & 7;            // expert id (4096-token chunks)
    const int eTma = b_estride ? e : 0;
    const float* Bp = bias + (b_estride ? e * b_estride : 0);

    const int wm = wid & 1;
    const int wn = wid >> 1;

    // ldmatrix lane-derived components + hoisted swizzle
    const int aRow  = (lane & 7) + ((lane >> 3) & 1) * 8;
    const int aBSel = (lane >> 4) * 16;
    const int bRow  = (lane & 7) + ((lane >> 4) & 1) * 8;
    const int bBSel = ((lane >> 3) & 1) * 16;
    const uint32_t xA = (uint32_t)((aRow & 7) << 4);
    const uint32_t xB = (uint32_t)((bRow & 7) << 4);
    uint32_t rowA[4], rowB[4], ktA[4], ktB[4];
#pragma unroll
    for (int i = 0; i < 4; i++)
        rowA[i] = (uint32_t)((wm * 64 + i * 16 + aRow) * 128);
#pragma unroll
    for (int j = 0; j < 4; j++)
        rowB[j] = (uint32_t)((wn * 64 + j * 16 + bRow) * 128);
#pragma unroll
    for (int t = 0; t < 4; t++) {
        ktA[t] = (uint32_t)(t * 32 + aBSel) ^ xA;
        ktB[t] = (uint32_t)(t * 32 + bBSel) ^ xB;
    }

    const uint32_t mbF = sb + MBOFF;           // full[0..2]
    const uint32_t mbE = sb + MBOFF + 24;      // empty[0..2]
    if (tid == 0) {
#pragma unroll
        for (int i = 0; i < NSTG; i++) {
            MBARRIER_INIT(mbF + 8 * i, 1);
            MBARRIER_INIT(mbE + 8 * i, 4);
        }
    }
    __syncthreads();

    float acc[4][8][4];
#pragma unroll
    for (int i = 0; i < 4; i++)
#pragma unroll
        for (int j = 0; j < 8; j++)
#pragma unroll
            for (int q = 0; q < 4; q++) acc[i][j][q] = 0.f;

    const int nst = K / 32;

    auto issue = [&](int s) {                  // single-thread (tid 0)
        const int buf = s % NSTG;
        const uint32_t m = mbF + 8 * buf;
        MBARRIER_EXPECT_TX(m, STG);
        const uint32_t dstA = sb + (uint32_t)buf * STG;
        tma3d(dstA,         &mapA, s * 32, row0, 0,    m);
        tma3d(dstA + 16384, &mapB, s * 32, col0, eTma, m);
    };

    if (tid == 0) { issue(0); issue(1); }

    int cbuf = 0, cph = 0;                     // consumer cursor (per thread)
    int ebuf = 0, eph = 0;                     // producer empty-wait cursor

    for (int s = 0; s < nst; ++s) {
        if (tid == 0 && s + 2 < nst) {
            const int i = s + 2;
            if (i >= NSTG) {                   // buffer reused: wait consumers
                MBARRIER_WAIT_PARITY(mbE + 8 * ebuf, eph);
                if (++ebuf == NSTG) { ebuf = 0; eph ^= 1; }
            }
            issue(i);
        }
        MBARRIER_WAIT_PARITY(mbF + 8 * cbuf, cph);   // per-warp full wait

        const uint32_t stgA = sb + (uint32_t)cbuf * STG;
#pragma unroll
        for (int kk = 0; kk < 4; ++kk) {
            const uint32_t sbA = stgA + ktA[kk];
            const uint32_t sbB = stgA + 16384 + ktB[kk];
            uint32_t af[4][4], bf[4][4];
#pragma unroll
            for (int i = 0; i < 4; ++i)
                ldsm4(af[i][0], af[i][1], af[i][2], af[i][3], sbA + rowA[i]);
#pragma unroll
            for (int j = 0; j < 4; ++j)
                ldsm4(bf[j][0], bf[j][1], bf[j][2], bf[j][3], sbB + rowB[j]);
#pragma unroll
            for (int i = 0; i < 4; ++i)
#pragma unroll
                for (int j = 0; j < 4; ++j) {
                    mma_tf32(acc[i][2 * j],     af[i], bf[j][0], bf[j][1]);
                    mma_tf32(acc[i][2 * j + 1], af[i], bf[j][2], bf[j][3]);
                }
        }
        if (lane == 0) MBARRIER_ARRIVE(mbE + 8 * cbuf);   // warp done with buf
        if (++cbuf == NSTG) { cbuf = 0; cph ^= 1; }
    }

    epilogue<GELU, RESID, ROUND_OUT>(acc, Bp, resid, C, row0, col0, OUTD, wm, wn, lane);
}

// ---------------- fallback: cp.async tf32 GEMM (R13, proven) -----------------
template<bool GELU, bool RESID, bool ROUND_OUT>
__global__ void __launch_bounds__(128, 2)
tc_gemm(const float* __restrict__ A, const float* __restrict__ W,
        const float* __restrict__ bias, const float* __restrict__ resid,
        float* __restrict__ C, int K, int OUTD,
        size_t w_estride, int b_estride)
{
    extern __shared__ char smem[];
    const uint32_t sb = smem_u32(smem);
    const int tid  = threadIdx.x;
    const int wid  = tid >> 5;
    const int lane = tid & 31;
    const int row0 = blockIdx.y * 128;
    const int col0 = blockIdx.x * 128;

    const int e = (row0 >> 12) & 7;
    const float* Wp = W + (w_estride ? (size_t)e * w_estride : 0);
    const float* Bp = bias + (b_estride ? e * b_estride : 0);

    const int wm = wid & 1;
    const int wn = wid >> 1;

    const int aRow  = (lane & 7) + ((lane >> 3) & 1) * 8;
    const int aBSel = (lane >> 4) * 16;
    const int bRow  = (lane & 7) + ((lane >> 4) & 1) * 8;
    const int bBSel = ((lane >> 3) & 1) * 16;
    const uint32_t xA = (uint32_t)((aRow & 7) << 4);
    const uint32_t xB = (uint32_t)((bRow & 7) << 4);
    uint32_t rowA[4], rowB[4], ktA[4], ktB[4];
#pragma unroll
    for (int i = 0; i < 4; i++)
        rowA[i] = (uint32_t)((wm * 64 + i * 16 + aRow) * 128);
#pragma unroll
    for (int j = 0; j < 4; j++)
        rowB[j] = (uint32_t)((wn * 64 + j * 16 + bRow) * 128);
#pragma unroll
    for (int t = 0; t < 4; t++) {
        ktA[t] = (uint32_t)(t * 32 + aBSel) ^ xA;
        ktB[t] = (uint32_t)(t * 32 + bBSel) ^ xB;
    }

    const int sr = tid >> 3;
    const int sq = tid & 7;
    const uint32_t stgOff = swz((uint32_t)(sr * 128 + sq * 16));

    const float* aCur = A  + (size_t)(row0 + sr) * K + sq * 4;
    const float* bCur = Wp + (size_t)(col0 + sr) * K + sq * 4;

    float acc[4][8][4];
#pragma unroll
    for (int i = 0; i < 4; i++)
#pragma unroll
        for (int j = 0; j < 8; j++)
#pragma unroll
            for (int q = 0; q < 4; q++) acc[i][j][q] = 0.f;

    const int nst = K / 32;
    int issueBuf = 0;
    auto issue = [&]() {
        const uint32_t base = sb + (uint32_t)issueBuf * STG;
#pragma unroll
        for (int i = 0; i < 8; i++)
            cp16(base + stgOff + (uint32_t)(i * 16 * 128),
                 aCur + (size_t)i * 16 * K);
#pragma unroll
        for (int i = 0; i < 8; i++)
            cp16(base + 16384 + stgOff + (uint32_t)(i * 16 * 128),
                 bCur + (size_t)i * 16 * K);
        cp_commit();
        aCur += 32; bCur += 32;
        issueBuf = (issueBuf + 1 == NSTG) ? 0 : issueBuf + 1;
    };

    issue(); issue();

    int curBuf = 0;
    for (int s = 0; s < nst; ++s) {
        if (s + 1 < nst) cp_wait<1>();
        else             cp_wait<0>();
        __syncthreads();
        if (s + 2 < nst) issue();

        const uint32_t stgA = sb + (uint32_t)curBuf * STG;
        curBuf = (curBuf + 1 == NSTG) ? 0 : curBuf + 1;
#pragma unroll
        for (int kk = 0; kk < 4; ++kk) {
            const uint32_t sbA = stgA + ktA[kk];
            const uint32_t sbB = stgA + 16384 + ktB[kk];
            uint32_t af[4][4], bf[4][4];
#pragma unroll
            for (int i = 0; i < 4; ++i)
                ldsm4(af[i][0], af[i][1], af[i][2], af[i][3], sbA + rowA[i]);
#pragma unroll
            for (int j = 0; j < 4; ++j)
                ldsm4(bf[j][0], bf[j][1], bf[j][2], bf[j][3], sbB + rowB[j]);
#pragma unroll
            for (int i = 0; i < 4; ++i)
#pragma unroll
                for (int j = 0; j < 4; ++j) {
                    mma_tf32(acc[i][2 * j],     af[i], bf[j][0], bf[j][1]);
                    mma_tf32(acc[i][2 * j + 1], af[i], bf[j][2], bf[j][3]);
                }
        }
    }

    epilogue<GELU, RESID, ROUND_OUT>(acc, Bp, resid, C, row0, col0, OUTD, wm, wn, lane);
}

// ---------------- host: tensor-map encoding via runtime entry point ----------
typedef CUresult (CUDAAPI *tmap_encode_t)(
    CUtensorMap*, CUtensorMapDataType, cuuint32_t, void*,
    const cuuint64_t*, const cuuint64_t*, const cuuint32_t*, const cuuint32_t*,
    CUtensorMapInterleave, CUtensorMapSwizzle, CUtensorMapL2promotion,
    CUtensorMapFloatOOBfill);

static bool encode3d(tmap_encode_t fn, CUtensorMap* m, void* base,
                     uint64_t d0, uint64_t d1, uint64_t d2)
{
    cuuint64_t dims[3]    = {d0, d1, d2};
    cuuint64_t strides[2] = {d0 * 4, d0 * d1 * 4};
    cuuint32_t box[3]     = {32, 128, 1};
    cuuint32_t estr[3]    = {1, 1, 1};
    return fn(m, CU_TENSOR_MAP_DATA_TYPE_FLOAT32, 3, base, dims, strides, box,
              estr, CU_TENSOR_MAP_INTERLEAVE_NONE, CU_TENSOR_MAP_SWIZZLE_128B,
              CU_TENSOR_MAP_L2_PROMOTION_L2_128B,
              CU_TENSOR_MAP_FLOAT_OOB_FILL_NONE) == CUDA_SUCCESS;
}

// ---------------- launch ------------------------------------------------------
extern "C" void kernel_launch(void* const* d_in, const int* in_sizes, int n_in,
                              void* d_out, int out_size)
{
    const float* x      = (const float*)d_in[0];
    const float* ln_g   = (const float*)d_in[1];
    const float* ln_b   = (const float*)d_in[2];
    const float* attn_w = (const float*)d_in[3];
    const float* attn_b = (const float*)d_in[4];
    /* gate_w d_in[5] unused */
    const float* fc1_w  = (const float*)d_in[6];
    const float* fc1_b  = (const float*)d_in[7];
    const float* fc2_w  = (const float*)d_in[8];
    const float* fc2_b  = (const float*)d_in[9];
    const float* next_w = (const float*)d_in[10];
    const float* next_b = (const float*)d_in[11];
    float* out = (float*)d_out;

    void *p_norm, *p_xattn, *p_h, *p_y, *p_wr;
    cudaGetSymbolAddress(&p_norm,  g_norm);
    cudaGetSymbolAddress(&p_xattn, g_xattn);
    cudaGetSymbolAddress(&p_h,     g_h);
    cudaGetSymbolAddress(&p_y,     g_y);
    cudaGetSymbolAddress(&p_wr,    g_wr);
    float* norm  = (float*)p_norm;
    float* xattn = (float*)p_xattn;
    float* hbuf  = (float*)p_h;
    float* ybuf  = (float*)p_y;
    float* wr    = (float*)p_wr;

    // 0) pre-round all weights to tf32 (single fused launch, 4 f4/thread)
    round_all<<<(unsigned)((N4_TOTAL + 1023) / 1024), 256>>>(
        (const float4*)attn_w, (const float4*)next_w,
        (const float4*)fc1_w,  (const float4*)fc2_w, (float4*)wr);

    // 1) LayerNorm (tf32-rounded output)
    ln_kernel<<<NTOK / 8, 256>>>(x, ln_g, ln_b, norm);

    // try TMA path: encode 8 tensor maps
    tmap_encode_t enc = nullptr;
    {
        void* fp = nullptr;
        cudaDriverEntryPointQueryResult qr;
#if CUDART_VERSION >= 12050
        cudaGetDriverEntryPointByVersion("cuTensorMapEncodeTiled", &fp, 12000,
                                         cudaEnableDefault, &qr);
#else
        cudaGetDriverEntryPoint("cuTensorMapEncodeTiled", &fp,
                                cudaEnableDefault, &qr);
#endif
        if (fp && qr == cudaDriverEntryPointSuccess) enc = (tmap_encode_t)fp;
    }

    CUtensorMap mAttnA, mAttnB, mFc1A, mFc1B, mFc2A, mFc2B, mNextA, mNextB;
    bool tmaOK = (enc != nullptr);
    if (tmaOK) {
        tmaOK = tmaOK && encode3d(enc, &mAttnA, norm,          DMODEL, NTOK,  1);
        tmaOK = tmaOK && encode3d(enc, &mAttnB, wr + WR_ATTN,  DMODEL, DMODEL, 1);
        tmaOK = tmaOK && encode3d(enc, &mFc1A,  xattn,         DMODEL, NTOK,  1);
        tmaOK = tmaOK && encode3d(enc, &mFc1B,  wr + WR_FC1,   DMODEL, HID,   NEXP);
        tmaOK = tmaOK && encode3d(enc, &mFc2A,  hbuf,          HID,    NTOK,  1);
        tmaOK = tmaOK && encode3d(enc, &mFc2B,  wr + WR_FC2,   HID,    DMODEL, NEXP);
        tmaOK = tmaOK && encode3d(enc, &mNextA, ybuf,          DMODEL, NTOK,  1);
        tmaOK = tmaOK && encode3d(enc, &mNextB, wr + WR_NEXT,  DMODEL, DMODEL, 1);
    }

    if (tmaOK) {
        auto kA = tc_gemm_tma<false, true,  true>;
        auto k1 = tc_gemm_tma<true,  false, true>;
        auto k2 = tc_gemm_tma<false, false, true>;
        auto kN = tc_gemm_tma<true,  false, false>;
        cudaFuncSetAttribute(kA, cudaFuncAttributeMaxDynamicSharedMemorySize, SMEM_TMA);
        cudaFuncSetAttribute(k1, cudaFuncAttributeMaxDynamicSharedMemorySize, SMEM_TMA);
        cudaFuncSetAttribute(k2, cudaFuncAttributeMaxDynamicSharedMemorySize, SMEM_TMA);
        cudaFuncSetAttribute(kN, cudaFuncAttributeMaxDynamicSharedMemorySize, SMEM_TMA);

        kA<<<dim3(DMODEL / 128, NTOK / 128), 128, SMEM_TMA>>>(
            mAttnA, mAttnB, attn_b, x, xattn, DMODEL, DMODEL, 0);
        k1<<<dim3(HID / 128, NTOK / 128), 128, SMEM_TMA>>>(
            mFc1A, mFc1B, fc1_b, nullptr, hbuf, DMODEL, HID, HID);
        k2<<<dim3(DMODEL / 128, NTOK / 128), 128, SMEM_TMA>>>(
            mFc2A, mFc2B, fc2_b, nullptr, ybuf, HID, DMODEL, DMODEL);
        kN<<<dim3(DMODEL / 128, NTOK / 128), 128, SMEM_TMA>>>(
            mNextA, mNextB, next_b, nullptr, out, DMODEL, DMODEL, 0);
    } else {
        // fallback: proven cp.async path
        auto kA = tc_gemm<false, true,  true>;
        auto k1 = tc_gemm<true,  false, true>;
        auto k2 = tc_gemm<false, false, true>;
        auto kN = tc_gemm<true,  false, false>;
        cudaFuncSetAttribute(kA, cudaFuncAttributeMaxDynamicSharedMemorySize, SMEM_CPA);
        cudaFuncSetAttribute(k1, cudaFuncAttributeMaxDynamicSharedMemorySize, SMEM_CPA);
        cudaFuncSetAttribute(k2, cudaFuncAttributeMaxDynamicSharedMemorySize, SMEM_CPA);
        cudaFuncSetAttribute(kN, cudaFuncAttributeMaxDynamicSharedMemorySize, SMEM_CPA);

        kA<<<dim3(DMODEL / 128, NTOK / 128), 128, SMEM_CPA>>>(
            norm, wr + WR_ATTN, attn_b, x, xattn, DMODEL, DMODEL, 0, 0);
        k1<<<dim3(HID / 128, NTOK / 128), 128, SMEM_CPA>>>(
            xattn, wr + WR_FC1, fc1_b, nullptr, hbuf, DMODEL, HID,
            (size_t)HID * DMODEL, HID);
        k2<<<dim3(DMODEL / 128, NTOK / 128), 128, SMEM_CPA>>>(
            hbuf, wr + WR_FC2, fc2_b, nullptr, ybuf, HID, DMODEL,
            (size_t)DMODEL * HID, DMODEL);
        kN<<<dim3(DMODEL / 128, NTOK / 128), 128, SMEM_CPA>>>(
            ybuf, wr + WR_NEXT, next_b, nullptr, out, DMODEL, DMODEL, 0, 0);
    }
}